// round 13
// baseline (speedup 1.0000x reference)
#include <cuda_runtime.h>
#include <cuda_bf16.h>
#include <math.h>
#include <stdint.h>

// ---------------- problem constants ----------------
constexpr int B = 512, T = 64, S = 128, A = 32, H = 1024, R = 1024;
constexpr int KP = S + A;     // 160
constexpr int N3 = 3 * R;     // 3072
constexpr int NO = 2 * S;     // 256
constexpr int SK = 4;

constexpr int NTHR = 256;

constexpr size_t OFF_MEAN  = 0;
constexpr size_t OFF_STD   = OFF_MEAN  + (size_t)B * T * S;
constexpr size_t OFF_STATE = OFF_STD   + (size_t)B * T * S;
constexpr size_t OFF_BEL   = OFF_STATE + (size_t)B * T * S;
constexpr size_t OFF_PREV  = OFF_BEL   + (size_t)B * T * R;

// ---------------- device scratch ----------------
__device__ float g_gi[B * N3];
__device__ float g_gh[B * N3];
__device__ float g_belief[B * R];
__device__ float g_mo[SK * B * NO];

__device__ __nv_bfloat16 g_x_hi[B * H],   g_x_lo[B * H];
__device__ __nv_bfloat16 g_bel_hi[B * R], g_bel_lo[B * R];
__device__ __nv_bfloat16 g_h_hi[B * H],   g_h_lo[B * H];
__device__ __nv_bfloat16 g_Wpr_hi[H * KP], g_Wpr_lo[H * KP];
__device__ __nv_bfloat16 g_Wih_hi[N3 * H], g_Wih_lo[N3 * H];
__device__ __nv_bfloat16 g_Whh_hi[N3 * R], g_Whh_lo[N3 * R];
__device__ __nv_bfloat16 g_Wh1_hi[H * R],  g_Wh1_lo[H * R];
__device__ __nv_bfloat16 g_Wou_hi[NO * H], g_Wou_lo[NO * H];

// ---------------- portable PTX helpers (sm_80+) ----------------
__device__ __forceinline__ uint32_t smem_to_u32(const void* p) {
    uint32_t a;
    asm("{ .reg .u64 t; cvta.to.shared.u64 t, %1; cvt.u32.u64 %0, t; }" : "=r"(a) : "l"(p));
    return a;
}
__device__ __forceinline__ void cp16(uint32_t saddr, const void* gaddr) {
    asm volatile("cp.async.cg.shared.global [%0], [%1], 16;" :: "r"(saddr), "l"(gaddr) : "memory");
}
__device__ __forceinline__ void cp_commit() { asm volatile("cp.async.commit_group;" ::: "memory"); }
__device__ __forceinline__ void cp_wait1()  { asm volatile("cp.async.wait_group 1;" ::: "memory"); }

__device__ __forceinline__ void ldsm4(uint32_t a, uint32_t& r0, uint32_t& r1,
                                      uint32_t& r2, uint32_t& r3) {
    asm volatile("ldmatrix.sync.aligned.m8n8.x4.shared.b16 {%0,%1,%2,%3}, [%4];"
                 : "=r"(r0), "=r"(r1), "=r"(r2), "=r"(r3) : "r"(a));
}
__device__ __forceinline__ void mma_bf16(float* c, const uint32_t* a, const uint32_t* b) {
    asm volatile("mma.sync.aligned.m16n8k16.row.col.f32.bf16.bf16.f32 "
                 "{%0,%1,%2,%3},{%4,%5,%6,%7},{%8,%9},{%0,%1,%2,%3};"
                 : "+f"(c[0]), "+f"(c[1]), "+f"(c[2]), "+f"(c[3])
                 : "r"(a[0]), "r"(a[1]), "r"(a[2]), "r"(a[3]), "r"(b[0]), "r"(b[1]));
}
__device__ __forceinline__ float elu1(float v) { return (v > 0.f) ? v : expm1f(v); }

// reparam sample for (b, s) at time tm1 from g_mo partials (fixed z-order)
__device__ __forceinline__ void sample_state(int b, int s,
        const float* __restrict__ b_out, const float* __restrict__ noise, int tm1,
        float& mean, float& sd, float& st) {
    mean = b_out[s];
    float raw = b_out[S + s];
    #pragma unroll
    for (int z = 0; z < SK; z++) {
        mean += g_mo[(size_t)z * B * NO + (size_t)b * NO + s];
        raw  += g_mo[(size_t)z * B * NO + (size_t)b * NO + S + s];
    }
    float sp = fmaxf(raw, 0.f) + log1pf(expf(-fabsf(raw)));
    sd = sp + 0.1f;
    float eps = noise[(size_t)b * T * S + (size_t)tm1 * S + s];
    st = fmaf(sd, eps, mean);
}

// ---------------- init ----------------
__global__ void init_k(const float* __restrict__ belief0) {
    int idx = blockIdx.x * blockDim.x + threadIdx.x;
    if (idx < B * R) {
        float v = belief0[idx];
        g_belief[idx] = v;
        __nv_bfloat16 h = __float2bfloat16(v);
        g_bel_hi[idx] = h;
        g_bel_lo[idx] = __float2bfloat16(v - __bfloat162float(h));
    }
}

// ---------------- weight prep: W[K][N] -> hi/lo[N][K] ----------------
__global__ void prep_w(const float* __restrict__ W, __nv_bfloat16* __restrict__ hi,
                       __nv_bfloat16* __restrict__ lo, int K, int N) {
    int idx = blockIdx.x * blockDim.x + threadIdx.x;
    if (idx >= N * K) return;
    int n = idx / K, k = idx % K;
    float v = W[(size_t)k * N + n];
    __nv_bfloat16 h = __float2bfloat16(v);
    hi[idx] = h;
    lo[idx] = __float2bfloat16(v - __bfloat162float(h));
}

// ---------------- bf16-split tensor-core GEMM tile, 3-stage pipeline ---------
// EPI: 0 = acc+bias fp32; 2 = elu(acc+bias) -> bf16 hi/lo; 3 = raw fp32 partial
// PACKA: A = [state | action_t]; state computed INLINE from g_mo/noise (t>0)
//        or read from priorSrc (t==0); writeOut CTAs also emit mean/std/state.
template<int BM, int BN, int WRM, int WRN, int EPI, int PACKA>
__device__ __forceinline__ void gemm_tile(char* smem,
    const __nv_bfloat16* __restrict__ Ahi, const __nv_bfloat16* __restrict__ Alo,
    const __nv_bfloat16* __restrict__ Bhi, const __nv_bfloat16* __restrict__ Blo,
    const float* __restrict__ bias, float* __restrict__ Cf,
    __nv_bfloat16* __restrict__ Chi, __nv_bfloat16* __restrict__ Clo,
    const float* __restrict__ priorSrc, const float* __restrict__ actSrc,
    const float* __restrict__ noiseSrc, const float* __restrict__ biasOut,
    float* __restrict__ outPtr, int writeOut, int tstep,
    int m0, int n0, int N, int K, int kz0, int KS)
{
    constexpr int THREADS = WRM * WRN * 32;
    constexpr int WTM = BM / WRM, WTN = BN / WRN;
    constexpr int MF = WTM / 16, NF = WTN / 8;
    constexpr int RS = 80;
    constexpr uint32_t OFS_AH = 0;
    constexpr uint32_t OFS_AL = (uint32_t)BM * RS;
    constexpr uint32_t OFS_BH = 2u * BM * RS;
    constexpr uint32_t OFS_BL = 2u * BM * RS + (uint32_t)BN * RS;
    constexpr uint32_t BUFSZ  = 2u * (BM + BN) * RS;

    const uint32_t sb = smem_to_u32(smem);
    const int tid = threadIdx.x;
    const int wid = tid >> 5, lane = tid & 31;
    const int wm = wid / WRN, wn = wid % WRN;

    const __nv_bfloat16* s0 = PACKA ? nullptr : Ahi + (size_t)m0 * K + kz0;
    const __nv_bfloat16* s1 = PACKA ? nullptr : Alo + (size_t)m0 * K + kz0;
    const __nv_bfloat16* s2 = Bhi + (size_t)n0 * K + kz0;
    const __nv_bfloat16* s3 = Blo + (size_t)n0 * K + kz0;

    const int NC = KS / 32;
    float acc[MF][NF][4];
    #pragma unroll
    for (int i = 0; i < MF; i++)
        #pragma unroll
        for (int j = 0; j < NF; j++)
            #pragma unroll
            for (int q = 0; q < 4; q++) acc[i][j][q] = 0.f;

    auto load_async = [&](int c, int buf) {
        uint32_t base = sb + (uint32_t)buf * BUFSZ;
        if constexpr (!PACKA) {
            constexpr int PPT = (BM + BN) * 8 / THREADS;
            #pragma unroll
            for (int i = 0; i < PPT; i++) {
                int p = tid + i * THREADS;
                const __nv_bfloat16* s;
                uint32_t ofs;
                int local;
                if (p < BM * 4)                   { s = s0; ofs = OFS_AH; local = p; }
                else if (p < 2 * BM * 4)          { s = s1; ofs = OFS_AL; local = p - BM * 4; }
                else if (p < 2 * BM * 4 + BN * 4) { s = s2; ofs = OFS_BH; local = p - 2 * BM * 4; }
                else                              { s = s3; ofs = OFS_BL; local = p - 2 * BM * 4 - BN * 4; }
                int row = local >> 2, k16 = local & 3;
                cp16(base + ofs + (uint32_t)row * RS + (uint32_t)k16 * 16,
                     s + (size_t)row * K + c * 32 + k16 * 8);
            }
        } else {
            constexpr int BPPT = BN * 8 / THREADS;
            #pragma unroll
            for (int i = 0; i < BPPT; i++) {
                int p = tid + i * THREADS;
                const __nv_bfloat16* s = (p < BN * 4) ? s2 : s3;
                uint32_t ofs = (p < BN * 4) ? OFS_BH : OFS_BL;
                int local = (p < BN * 4) ? p : p - BN * 4;
                int row = local >> 2, k16 = local & 3;
                cp16(base + ofs + (uint32_t)row * RS + (uint32_t)k16 * 16,
                     s + (size_t)row * K + c * 32 + k16 * 8);
            }
        }
    };

    auto load_A_pack = [&](int c, int buf) {
        if constexpr (PACKA) {
            char* bm = smem + (uint32_t)buf * BUFSZ;
            constexpr int APPT = BM * 4 / THREADS;
            #pragma unroll
            for (int i = 0; i < APPT; i++) {
                int slot = tid + i * THREADS;
                int row = slot >> 2, g8 = slot & 3;
                int kb = c * 32 + g8 * 8;
                int b = m0 + row;
                __nv_bfloat16 hv[8], lv[8];
                if (kb < S) {
                    if (tstep == 0) {
                        #pragma unroll
                        for (int j = 0; j < 8; j++) {
                            float v = priorSrc[(size_t)b * S + kb + j];
                            __nv_bfloat16 h = __float2bfloat16(v);
                            hv[j] = h;
                            lv[j] = __float2bfloat16(v - __bfloat162float(h));
                        }
                    } else {
                        #pragma unroll
                        for (int j = 0; j < 8; j++) {
                            int col = kb + j;
                            float mean, sd, v;
                            sample_state(b, col, biasOut, noiseSrc, tstep - 1, mean, sd, v);
                            if (writeOut) {
                                size_t o = (size_t)b * T * S + (size_t)(tstep - 1) * S + col;
                                outPtr[OFF_MEAN + o]  = mean;
                                outPtr[OFF_STD + o]   = sd;
                                outPtr[OFF_STATE + o] = v;
                            }
                            __nv_bfloat16 h = __float2bfloat16(v);
                            hv[j] = h;
                            lv[j] = __float2bfloat16(v - __bfloat162float(h));
                        }
                    }
                } else {
                    #pragma unroll
                    for (int j = 0; j < 8; j++) {
                        float v = actSrc[(size_t)b * T * A + (size_t)tstep * A + (kb + j - S)];
                        __nv_bfloat16 h = __float2bfloat16(v);
                        hv[j] = h;
                        lv[j] = __float2bfloat16(v - __bfloat162float(h));
                    }
                }
                *(uint4*)(bm + OFS_AH + (uint32_t)row * RS + (uint32_t)g8 * 16) = *(uint4*)hv;
                *(uint4*)(bm + OFS_AL + (uint32_t)row * RS + (uint32_t)g8 * 16) = *(uint4*)lv;
            }
        }
    };

    auto mma_chunk = [&](int buf) {
        uint32_t base = sb + (uint32_t)buf * BUFSZ;
        const int grp = lane >> 3, l8 = lane & 7;
        #pragma unroll
        for (int ks = 0; ks < 2; ks++) {
            uint32_t ahi[MF][4], alo[MF][4], bhi[NF][2], blo[NF][2];
            uint32_t arow = (uint32_t)(wm * WTM + (grp & 1) * 8 + l8);
            uint32_t acol = (uint32_t)(ks * 32 + (grp >> 1) * 16);
            #pragma unroll
            for (int mt = 0; mt < MF; mt++) {
                uint32_t r = (arow + mt * 16) * RS + acol;
                ldsm4(base + OFS_AH + r, ahi[mt][0], ahi[mt][1], ahi[mt][2], ahi[mt][3]);
                ldsm4(base + OFS_AL + r, alo[mt][0], alo[mt][1], alo[mt][2], alo[mt][3]);
            }
            uint32_t brow = (uint32_t)(wn * WTN + (grp >> 1) * 8 + l8);
            uint32_t bcol = (uint32_t)(ks * 32 + (grp & 1) * 16);
            #pragma unroll
            for (int np = 0; np < NF / 2; np++) {
                uint32_t r = (brow + np * 16) * RS + bcol;
                ldsm4(base + OFS_BH + r, bhi[2 * np][0], bhi[2 * np][1],
                      bhi[2 * np + 1][0], bhi[2 * np + 1][1]);
                ldsm4(base + OFS_BL + r, blo[2 * np][0], blo[2 * np][1],
                      blo[2 * np + 1][0], blo[2 * np + 1][1]);
            }
            #pragma unroll
            for (int mt = 0; mt < MF; mt++)
                #pragma unroll
                for (int nt = 0; nt < NF; nt++) {
                    mma_bf16(acc[mt][nt], ahi[mt], bhi[nt]);
                    mma_bf16(acc[mt][nt], ahi[mt], blo[nt]);
                    mma_bf16(acc[mt][nt], alo[mt], bhi[nt]);
                }
        }
    };

    load_A_pack(0, 0);
    load_async(0, 0); cp_commit();
    if (NC > 1) { load_A_pack(1, 1); load_async(1, 1); }
    cp_commit();
    for (int c = 0; c < NC; c++) {
        cp_wait1();
        __syncthreads();
        mma_chunk(c % 3);
        if (c + 2 < NC) { load_A_pack(c + 2, (c + 2) % 3); load_async(c + 2, (c + 2) % 3); }
        cp_commit();
    }

    #pragma unroll
    for (int mt = 0; mt < MF; mt++)
        #pragma unroll
        for (int nt = 0; nt < NF; nt++) {
            int m = m0 + wm * WTM + mt * 16 + (lane >> 2);
            int n = n0 + wn * WTN + nt * 8 + (lane & 3) * 2;
            if constexpr (EPI == 3) {
                *(float2*)&Cf[(size_t)m * N + n] =
                    make_float2(acc[mt][nt][0], acc[mt][nt][1]);
                *(float2*)&Cf[(size_t)(m + 8) * N + n] =
                    make_float2(acc[mt][nt][2], acc[mt][nt][3]);
            } else if constexpr (EPI == 2) {
                float b0 = bias[n], b1 = bias[n + 1];
                float v00 = elu1(acc[mt][nt][0] + b0), v01 = elu1(acc[mt][nt][1] + b1);
                float v10 = elu1(acc[mt][nt][2] + b0), v11 = elu1(acc[mt][nt][3] + b1);
                __nv_bfloat16 h00 = __float2bfloat16(v00), h01 = __float2bfloat16(v01);
                __nv_bfloat16 h10 = __float2bfloat16(v10), h11 = __float2bfloat16(v11);
                __nv_bfloat162 hi0; hi0.x = h00; hi0.y = h01;
                __nv_bfloat162 hi1; hi1.x = h10; hi1.y = h11;
                __nv_bfloat162 lo0, lo1;
                lo0.x = __float2bfloat16(v00 - __bfloat162float(h00));
                lo0.y = __float2bfloat16(v01 - __bfloat162float(h01));
                lo1.x = __float2bfloat16(v10 - __bfloat162float(h10));
                lo1.y = __float2bfloat16(v11 - __bfloat162float(h11));
                *(__nv_bfloat162*)&Chi[(size_t)m * N + n] = hi0;
                *(__nv_bfloat162*)&Clo[(size_t)m * N + n] = lo0;
                *(__nv_bfloat162*)&Chi[(size_t)(m + 8) * N + n] = hi1;
                *(__nv_bfloat162*)&Clo[(size_t)(m + 8) * N + n] = lo1;
            } else {
                float b0 = bias[n], b1 = bias[n + 1];
                *(float2*)&Cf[(size_t)m * N + n] =
                    make_float2(acc[mt][nt][0] + b0, acc[mt][nt][1] + b1);
                *(float2*)&Cf[(size_t)(m + 8) * N + n] =
                    make_float2(acc[mt][nt][2] + b0, acc[mt][nt][3] + b1);
            }
        }
}

// ---------------- wrappers ----------------

// proj (fused with reparam sample of previous step): grid(16, 8), 256 thr.
__global__ void __launch_bounds__(NTHR)
proj_k(const float* __restrict__ prior_state, const float* __restrict__ actions,
       const float* __restrict__ noise, const float* __restrict__ b_out,
       const float* __restrict__ b_proj, float* __restrict__ out, int t) {
    extern __shared__ char smem[];
    gemm_tile<64, 64, 2, 4, 2, 1>(smem, nullptr, nullptr, g_Wpr_hi, g_Wpr_lo,
        b_proj, nullptr, g_x_hi, g_x_lo,
        prior_state, actions, noise, b_out, out, blockIdx.x == 0, t,
        blockIdx.y * 64, blockIdx.x * 64, H, KP, 0, KP);
}

// gi = x @ Wih + b_ih. 384 tiles of 64x64, 128 thr, 3 CTAs/SM.
__global__ void __launch_bounds__(128, 3)
gi_k(const float* __restrict__ b_ih) {
    extern __shared__ char smem[];
    gemm_tile<64, 64, 2, 2, 0, 0>(smem, g_x_hi, g_x_lo, g_Wih_hi, g_Wih_lo,
        b_ih, g_gi, nullptr, nullptr,
        nullptr, nullptr, nullptr, nullptr, nullptr, 0, 0,
        blockIdx.y * 64, blockIdx.x * 64, N3, H, 0, H);
}

// combo: gh_{t+1} = belief @ Whh + b_hh (96 fat tiles) AND h1 (32 fat tiles).
__global__ void __launch_bounds__(NTHR)
combo_k(const float* __restrict__ b_hh, const float* __restrict__ b_h1) {
    extern __shared__ char smem[];
    int tk = blockIdx.x;
    if (tk < 96) {
        int mi = tk / 24, ni = tk % 24;
        gemm_tile<128, 128, 2, 4, 0, 0>(smem, g_bel_hi, g_bel_lo, g_Whh_hi, g_Whh_lo,
            b_hh, g_gh, nullptr, nullptr,
            nullptr, nullptr, nullptr, nullptr, nullptr, 0, 0,
            mi * 128, ni * 128, N3, R, 0, R);
    } else {
        int u = tk - 96;
        int mi = u / 8, ni = u % 8;
        gemm_tile<128, 128, 2, 4, 2, 0>(smem, g_bel_hi, g_bel_lo, g_Wh1_hi, g_Wh1_lo,
            b_h1, nullptr, g_h_hi, g_h_lo,
            nullptr, nullptr, nullptr, nullptr, nullptr, 0, 0,
            mi * 128, ni * 128, H, R, 0, R);
    }
}

// gh only (prologue, t = 0)
__global__ void __launch_bounds__(NTHR)
gh0_k(const float* __restrict__ b_hh) {
    extern __shared__ char smem[];
    int tk = blockIdx.x;
    int mi = tk / 24, ni = tk % 24;
    gemm_tile<128, 128, 2, 4, 0, 0>(smem, g_bel_hi, g_bel_lo, g_Whh_hi, g_Whh_lo,
        b_hh, g_gh, nullptr, nullptr,
        nullptr, nullptr, nullptr, nullptr, nullptr, 0, 0,
        mi * 128, ni * 128, N3, R, 0, R);
}

// out: [mean|raw] partials = h @ Wou over K-slice. grid(4,8,SK).
__global__ void __launch_bounds__(NTHR)
out_k() {
    extern __shared__ char smem[];
    int z = blockIdx.z;
    gemm_tile<64, 64, 2, 4, 3, 0>(smem, g_h_hi, g_h_lo, g_Wou_hi, g_Wou_lo,
        nullptr, g_mo + (size_t)z * B * NO, nullptr, nullptr,
        nullptr, nullptr, nullptr, nullptr, nullptr, 0, 0,
        blockIdx.y * 64, blockIdx.x * 64, NO, H, z * 256, 256);
}

// ---------------- GRU gate + belief update ----------------
__global__ void gate_k(float* __restrict__ out, int t) {
    int idx = blockIdx.x * blockDim.x + threadIdx.x;
    if (idx >= B * R) return;
    int b = idx / R, r = idx % R;
    size_t base = (size_t)b * N3;
    float ir = g_gi[base + r],          hr = g_gh[base + r];
    float iz = g_gi[base + R + r],      hz = g_gh[base + R + r];
    float in_ = g_gi[base + 2 * R + r], hn = g_gh[base + 2 * R + r];
    float rg = 1.f / (1.f + expf(-(ir + hr)));
    float zg = 1.f / (1.f + expf(-(iz + hz)));
    float ng = tanhf(in_ + rg * hn);
    float old = g_belief[idx];
    float nb = (1.f - zg) * ng + zg * old;
    g_belief[idx] = nb;
    __nv_bfloat16 h = __float2bfloat16(nb);
    g_bel_hi[idx] = h;
    g_bel_lo[idx] = __float2bfloat16(nb - __bfloat162float(h));
    size_t o = (size_t)b * T * R + (size_t)t * R + r;
    out[OFF_BEL + o]  = nb;
    out[OFF_PREV + o] = old;
}

// ---------------- final epilogue (only for t = T-1) ----------------
__global__ void epi_k(const float* __restrict__ noise,
                      const float* __restrict__ b_out,
                      float* __restrict__ out, int t) {
    int idx = blockIdx.x * blockDim.x + threadIdx.x;
    if (idx >= B * S) return;
    int b = idx / S, s = idx % S;
    float mean, sd, st;
    sample_state(b, s, b_out, noise, t, mean, sd, st);
    size_t o = (size_t)b * T * S + (size_t)t * S + s;
    out[OFF_MEAN + o]  = mean;
    out[OFF_STD + o]   = sd;
    out[OFF_STATE + o] = st;
}

// ---------------- launch ----------------
extern "C" void kernel_launch(void* const* d_in, const int* in_sizes, int n_in,
                              void* d_out, int out_size) {
    const float* prior_state = (const float*)d_in[0];
    const float* belief0     = (const float*)d_in[1];
    const float* actions     = (const float*)d_in[2];
    const float* noise       = (const float*)d_in[3];
    const float* W_proj = (const float*)d_in[4];
    const float* b_proj = (const float*)d_in[5];
    const float* W_ih   = (const float*)d_in[6];
    const float* b_ih   = (const float*)d_in[7];
    const float* W_hh   = (const float*)d_in[8];
    const float* b_hh   = (const float*)d_in[9];
    const float* W_h1   = (const float*)d_in[10];
    const float* b_h1   = (const float*)d_in[11];
    const float* W_out  = (const float*)d_in[12];
    const float* b_out  = (const float*)d_in[13];
    float* out = (float*)d_out;

    __nv_bfloat16 *p_Wpr_h, *p_Wpr_l, *p_Wih_h, *p_Wih_l, *p_Whh_h, *p_Whh_l;
    __nv_bfloat16 *p_Wh1_h, *p_Wh1_l, *p_Wou_h, *p_Wou_l;
    cudaGetSymbolAddress((void**)&p_Wpr_h, g_Wpr_hi);
    cudaGetSymbolAddress((void**)&p_Wpr_l, g_Wpr_lo);
    cudaGetSymbolAddress((void**)&p_Wih_h, g_Wih_hi);
    cudaGetSymbolAddress((void**)&p_Wih_l, g_Wih_lo);
    cudaGetSymbolAddress((void**)&p_Whh_h, g_Whh_hi);
    cudaGetSymbolAddress((void**)&p_Whh_l, g_Whh_lo);
    cudaGetSymbolAddress((void**)&p_Wh1_h, g_Wh1_hi);
    cudaGetSymbolAddress((void**)&p_Wh1_l, g_Wh1_lo);
    cudaGetSymbolAddress((void**)&p_Wou_h, g_Wou_hi);
    cudaGetSymbolAddress((void**)&p_Wou_l, g_Wou_lo);

    constexpr uint32_t SMEM_BIG = 3u * 2u * (128 + 128) * 80;  // 122880
    constexpr uint32_t SMEM_SML = 3u * 2u * (64 + 64) * 80;    // 61440
    cudaFuncSetAttribute((const void*)proj_k,  cudaFuncAttributeMaxDynamicSharedMemorySize, SMEM_SML);
    cudaFuncSetAttribute((const void*)gi_k,    cudaFuncAttributeMaxDynamicSharedMemorySize, SMEM_SML);
    cudaFuncSetAttribute((const void*)combo_k, cudaFuncAttributeMaxDynamicSharedMemorySize, SMEM_BIG);
    cudaFuncSetAttribute((const void*)gh0_k,   cudaFuncAttributeMaxDynamicSharedMemorySize, SMEM_BIG);
    cudaFuncSetAttribute((const void*)out_k,   cudaFuncAttributeMaxDynamicSharedMemorySize, SMEM_SML);

    // one-time per replay: init belief + weight split + gh_0
    init_k<<<(B * R + 255) / 256, 256>>>(belief0);
    prep_w<<<(H * KP + 255) / 256, 256>>>(W_proj, p_Wpr_h, p_Wpr_l, KP, H);
    prep_w<<<(N3 * H + 255) / 256, 256>>>(W_ih, p_Wih_h, p_Wih_l, H, N3);
    prep_w<<<(N3 * R + 255) / 256, 256>>>(W_hh, p_Whh_h, p_Whh_l, R, N3);
    prep_w<<<(H * R + 255) / 256, 256>>>(W_h1, p_Wh1_h, p_Wh1_l, R, H);
    prep_w<<<(NO * H + 255) / 256, 256>>>(W_out, p_Wou_h, p_Wou_l, H, NO);
    gh0_k<<<96, NTHR, SMEM_BIG>>>(b_hh);

    for (int t = 0; t < T; t++) {
        // x = elu([state|action_t] @ Wpr + b_proj); state computed inline from
        // g_mo (step t-1) + noise, outputs for t-1 written by n-tile-0 CTAs.
        proj_k<<<dim3(H / 64, B / 64), NTHR, SMEM_SML>>>(
            prior_state, actions, noise, b_out, b_proj, out, t);

        // gi = x @ Wih + b_ih  -- 384 small tiles, all-SM balanced
        gi_k<<<dim3(N3 / 64, B / 64), 128, SMEM_SML>>>(b_ih);

        // GRU gates -> new belief (+hi/lo), write beliefs + prev_beliefs
        gate_k<<<(B * R + 255) / 256, 256>>>(out, t);

        // gh_{t+1} + h1 in ONE wave (fat tiles; small tiles regressed in R12)
        combo_k<<<128, NTHR, SMEM_BIG>>>(b_hh, b_h1);

        // [mean|raw] partials = h @ Wou (split-K=4)
        out_k<<<dim3(NO / 64, B / 64, SK), NTHR, SMEM_SML>>>();
    }

    // final step's mean/std/state (no proj_{T} exists to emit them)
    epi_k<<<(B * S + 255) / 256, 256>>>(noise, b_out, out, T - 1);
}

// round 14
// speedup vs baseline: 1.0681x; 1.0681x over previous
#include <cuda_runtime.h>
#include <cuda_bf16.h>
#include <math.h>
#include <stdint.h>

// ---------------- problem constants ----------------
constexpr int B = 512, T = 64, S = 128, A = 32, H = 1024, R = 1024;
constexpr int KP = S + A;     // 160
constexpr int N3 = 3 * R;     // 3072
constexpr int NO = 2 * S;     // 256

constexpr int NTHR = 256;

constexpr size_t OFF_MEAN  = 0;
constexpr size_t OFF_STD   = OFF_MEAN  + (size_t)B * T * S;
constexpr size_t OFF_STATE = OFF_STD   + (size_t)B * T * S;
constexpr size_t OFF_BEL   = OFF_STATE + (size_t)B * T * S;
constexpr size_t OFF_PREV  = OFF_BEL   + (size_t)B * T * R;

// ---------------- device scratch ----------------
__device__ float g_gi[B * N3];
__device__ float g_gh[B * N3];
__device__ float g_belief[B * R];
__device__ float g_state [B * S];

__device__ __nv_bfloat16 g_x_hi[B * H],   g_x_lo[B * H];
__device__ __nv_bfloat16 g_bel_hi[B * R], g_bel_lo[B * R];
__device__ __nv_bfloat16 g_h_hi[B * H],   g_h_lo[B * H];
__device__ __nv_bfloat16 g_Wpr_hi[H * KP], g_Wpr_lo[H * KP];
__device__ __nv_bfloat16 g_Wih_hi[N3 * H], g_Wih_lo[N3 * H];
__device__ __nv_bfloat16 g_Whh_hi[N3 * R], g_Whh_lo[N3 * R];
__device__ __nv_bfloat16 g_Wh1_hi[H * R],  g_Wh1_lo[H * R];
__device__ __nv_bfloat16 g_WouP_hi[NO * H], g_WouP_lo[NO * H];  // PERMUTED rows

// ---------------- portable PTX helpers (sm_80+) ----------------
__device__ __forceinline__ uint32_t smem_to_u32(const void* p) {
    uint32_t a;
    asm("{ .reg .u64 t; cvta.to.shared.u64 t, %1; cvt.u32.u64 %0, t; }" : "=r"(a) : "l"(p));
    return a;
}
__device__ __forceinline__ void cp16(uint32_t saddr, const void* gaddr) {
    asm volatile("cp.async.cg.shared.global [%0], [%1], 16;" :: "r"(saddr), "l"(gaddr) : "memory");
}
__device__ __forceinline__ void cp_commit() { asm volatile("cp.async.commit_group;" ::: "memory"); }
__device__ __forceinline__ void cp_wait1()  { asm volatile("cp.async.wait_group 1;" ::: "memory"); }

__device__ __forceinline__ void ldsm4(uint32_t a, uint32_t& r0, uint32_t& r1,
                                      uint32_t& r2, uint32_t& r3) {
    asm volatile("ldmatrix.sync.aligned.m8n8.x4.shared.b16 {%0,%1,%2,%3}, [%4];"
                 : "=r"(r0), "=r"(r1), "=r"(r2), "=r"(r3) : "r"(a));
}
__device__ __forceinline__ void mma_bf16(float* c, const uint32_t* a, const uint32_t* b) {
    asm volatile("mma.sync.aligned.m16n8k16.row.col.f32.bf16.bf16.f32 "
                 "{%0,%1,%2,%3},{%4,%5,%6,%7},{%8,%9},{%0,%1,%2,%3};"
                 : "+f"(c[0]), "+f"(c[1]), "+f"(c[2]), "+f"(c[3])
                 : "r"(a[0]), "r"(a[1]), "r"(a[2]), "r"(a[3]), "r"(b[0]), "r"(b[1]));
}
__device__ __forceinline__ float elu1(float v) { return (v > 0.f) ? v : expm1f(v); }

// ---------------- init ----------------
__global__ void init_k(const float* __restrict__ prior_state,
                       const float* __restrict__ belief0) {
    int idx = blockIdx.x * blockDim.x + threadIdx.x;
    if (idx < B * R) {
        float v = belief0[idx];
        g_belief[idx] = v;
        __nv_bfloat16 h = __float2bfloat16(v);
        g_bel_hi[idx] = h;
        g_bel_lo[idx] = __float2bfloat16(v - __bfloat162float(h));
    }
    if (idx < B * S) g_state[idx] = prior_state[idx];
}

// ---------------- weight prep: W[K][N] -> hi/lo[N][K] ----------------
__global__ void prep_w(const float* __restrict__ W, __nv_bfloat16* __restrict__ hi,
                       __nv_bfloat16* __restrict__ lo, int K, int N) {
    int idx = blockIdx.x * blockDim.x + threadIdx.x;
    if (idx >= N * K) return;
    int n = idx / K, k = idx % K;
    float v = W[(size_t)k * N + n];
    __nv_bfloat16 h = __float2bfloat16(v);
    hi[idx] = h;
    lo[idx] = __float2bfloat16(v - __bfloat162float(h));
}

// prep W_out with PERMUTED row order: block sb of 64 rows = [mean s in
// sb*32..+32) | raw s in sb*32..+32)], so a 64-col tile holds matched pairs.
__global__ void prep_wou(const float* __restrict__ W, __nv_bfloat16* __restrict__ hi,
                         __nv_bfloat16* __restrict__ lo) {
    int idx = blockIdx.x * blockDim.x + threadIdx.x;
    if (idx >= NO * H) return;
    int np = idx / H, k = idx % H;
    int sb = np >> 6, w = np & 63;
    int orig = (w < 32) ? (sb * 32 + w) : (S + sb * 32 + (w - 32));
    float v = W[(size_t)k * NO + orig];
    __nv_bfloat16 h = __float2bfloat16(v);
    hi[idx] = h;
    lo[idx] = __float2bfloat16(v - __bfloat162float(h));
}

// ---------------- bf16-split tensor-core GEMM tile, 3-stage pipeline ---------
// EPI: 0 = acc+bias fp32; 2 = elu(acc+bias) -> bf16 hi/lo
//      4 = fused out+epi: stage to smem, softplus+sample, write outputs+state
// PACKA: A = [g_state | action_t] built on the fly (inline hi/lo split)
template<int BM, int BN, int WRM, int WRN, int EPI, int PACKA>
__device__ __forceinline__ void gemm_tile(char* smem,
    const __nv_bfloat16* __restrict__ Ahi, const __nv_bfloat16* __restrict__ Alo,
    const __nv_bfloat16* __restrict__ Bhi, const __nv_bfloat16* __restrict__ Blo,
    const float* __restrict__ bias, float* __restrict__ Cf,
    __nv_bfloat16* __restrict__ Chi, __nv_bfloat16* __restrict__ Clo,
    const float* __restrict__ stateSrc, const float* __restrict__ actSrc,
    const float* __restrict__ noiseSrc, const float* __restrict__ biasOut,
    float* __restrict__ outPtr, int tstep,
    int m0, int n0, int N, int K, int kz0, int KS)
{
    constexpr int THREADS = WRM * WRN * 32;
    constexpr int WTM = BM / WRM, WTN = BN / WRN;
    constexpr int MF = WTM / 16, NF = WTN / 8;
    constexpr int RS = 80;
    constexpr uint32_t OFS_AH = 0;
    constexpr uint32_t OFS_AL = (uint32_t)BM * RS;
    constexpr uint32_t OFS_BH = 2u * BM * RS;
    constexpr uint32_t OFS_BL = 2u * BM * RS + (uint32_t)BN * RS;
    constexpr uint32_t BUFSZ  = 2u * (BM + BN) * RS;

    const uint32_t sb = smem_to_u32(smem);
    const int tid = threadIdx.x;
    const int wid = tid >> 5, lane = tid & 31;
    const int wm = wid / WRN, wn = wid % WRN;

    const __nv_bfloat16* s0 = PACKA ? nullptr : Ahi + (size_t)m0 * K + kz0;
    const __nv_bfloat16* s1 = PACKA ? nullptr : Alo + (size_t)m0 * K + kz0;
    const __nv_bfloat16* s2 = Bhi + (size_t)n0 * K + kz0;
    const __nv_bfloat16* s3 = Blo + (size_t)n0 * K + kz0;

    const int NC = KS / 32;
    float acc[MF][NF][4];
    #pragma unroll
    for (int i = 0; i < MF; i++)
        #pragma unroll
        for (int j = 0; j < NF; j++)
            #pragma unroll
            for (int q = 0; q < 4; q++) acc[i][j][q] = 0.f;

    auto load_async = [&](int c, int buf) {
        uint32_t base = sb + (uint32_t)buf * BUFSZ;
        if constexpr (!PACKA) {
            constexpr int PPT = (BM + BN) * 8 / THREADS;
            #pragma unroll
            for (int i = 0; i < PPT; i++) {
                int p = tid + i * THREADS;
                const __nv_bfloat16* s;
                uint32_t ofs;
                int local;
                if (p < BM * 4)                   { s = s0; ofs = OFS_AH; local = p; }
                else if (p < 2 * BM * 4)          { s = s1; ofs = OFS_AL; local = p - BM * 4; }
                else if (p < 2 * BM * 4 + BN * 4) { s = s2; ofs = OFS_BH; local = p - 2 * BM * 4; }
                else                              { s = s3; ofs = OFS_BL; local = p - 2 * BM * 4 - BN * 4; }
                int row = local >> 2, k16 = local & 3;
                cp16(base + ofs + (uint32_t)row * RS + (uint32_t)k16 * 16,
                     s + (size_t)row * K + c * 32 + k16 * 8);
            }
        } else {
            constexpr int BPPT = BN * 8 / THREADS;
            #pragma unroll
            for (int i = 0; i < BPPT; i++) {
                int p = tid + i * THREADS;
                const __nv_bfloat16* s = (p < BN * 4) ? s2 : s3;
                uint32_t ofs = (p < BN * 4) ? OFS_BH : OFS_BL;
                int local = (p < BN * 4) ? p : p - BN * 4;
                int row = local >> 2, k16 = local & 3;
                cp16(base + ofs + (uint32_t)row * RS + (uint32_t)k16 * 16,
                     s + (size_t)row * K + c * 32 + k16 * 8);
            }
        }
    };

    auto load_A_pack = [&](int c, int buf) {
        if constexpr (PACKA) {
            char* bm = smem + (uint32_t)buf * BUFSZ;
            constexpr int APPT = BM * 4 / THREADS;
            #pragma unroll
            for (int i = 0; i < APPT; i++) {
                int slot = tid + i * THREADS;
                int row = slot >> 2, g8 = slot & 3;
                int kb = c * 32 + g8 * 8;
                __nv_bfloat16 hv[8], lv[8];
                #pragma unroll
                for (int j = 0; j < 8; j++) {
                    int col = kb + j;
                    float v = (col < S)
                        ? stateSrc[(size_t)(m0 + row) * S + col]
                        : actSrc[(size_t)(m0 + row) * T * A + (size_t)tstep * A + (col - S)];
                    __nv_bfloat16 h = __float2bfloat16(v);
                    hv[j] = h;
                    lv[j] = __float2bfloat16(v - __bfloat162float(h));
                }
                *(uint4*)(bm + OFS_AH + (uint32_t)row * RS + (uint32_t)g8 * 16) = *(uint4*)hv;
                *(uint4*)(bm + OFS_AL + (uint32_t)row * RS + (uint32_t)g8 * 16) = *(uint4*)lv;
            }
        }
    };

    auto mma_chunk = [&](int buf) {
        uint32_t base = sb + (uint32_t)buf * BUFSZ;
        const int grp = lane >> 3, l8 = lane & 7;
        #pragma unroll
        for (int ks = 0; ks < 2; ks++) {
            uint32_t ahi[MF][4], alo[MF][4], bhi[NF][2], blo[NF][2];
            uint32_t arow = (uint32_t)(wm * WTM + (grp & 1) * 8 + l8);
            uint32_t acol = (uint32_t)(ks * 32 + (grp >> 1) * 16);
            #pragma unroll
            for (int mt = 0; mt < MF; mt++) {
                uint32_t r = (arow + mt * 16) * RS + acol;
                ldsm4(base + OFS_AH + r, ahi[mt][0], ahi[mt][1], ahi[mt][2], ahi[mt][3]);
                ldsm4(base + OFS_AL + r, alo[mt][0], alo[mt][1], alo[mt][2], alo[mt][3]);
            }
            uint32_t brow = (uint32_t)(wn * WTN + (grp >> 1) * 8 + l8);
            uint32_t bcol = (uint32_t)(ks * 32 + (grp & 1) * 16);
            #pragma unroll
            for (int np = 0; np < NF / 2; np++) {
                uint32_t r = (brow + np * 16) * RS + bcol;
                ldsm4(base + OFS_BH + r, bhi[2 * np][0], bhi[2 * np][1],
                      bhi[2 * np + 1][0], bhi[2 * np + 1][1]);
                ldsm4(base + OFS_BL + r, blo[2 * np][0], blo[2 * np][1],
                      blo[2 * np + 1][0], blo[2 * np + 1][1]);
            }
            #pragma unroll
            for (int mt = 0; mt < MF; mt++)
                #pragma unroll
                for (int nt = 0; nt < NF; nt++) {
                    mma_bf16(acc[mt][nt], ahi[mt], bhi[nt]);
                    mma_bf16(acc[mt][nt], ahi[mt], blo[nt]);
                    mma_bf16(acc[mt][nt], alo[mt], bhi[nt]);
                }
        }
    };

    load_A_pack(0, 0);
    load_async(0, 0); cp_commit();
    if (NC > 1) { load_A_pack(1, 1); load_async(1, 1); }
    cp_commit();
    for (int c = 0; c < NC; c++) {
        cp_wait1();
        __syncthreads();
        mma_chunk(c % 3);
        if (c + 2 < NC) { load_A_pack(c + 2, (c + 2) % 3); load_async(c + 2, (c + 2) % 3); }
        cp_commit();
    }

    if constexpr (EPI == 4) {
        // fused out+epi: stage raw acc (64x64 permuted tile) through smem,
        // then softplus + reparam sample + write outputs and g_state.
        __syncthreads();  // all warps done reading tile smem
        float* stg = (float*)smem;  // 64 x 68 floats
        #pragma unroll
        for (int mt = 0; mt < MF; mt++)
            #pragma unroll
            for (int nt = 0; nt < NF; nt++) {
                int ml = wm * WTM + mt * 16 + (lane >> 2);
                int nl = wn * WTN + nt * 8 + (lane & 3) * 2;
                stg[ml * 68 + nl]           = acc[mt][nt][0];
                stg[ml * 68 + nl + 1]       = acc[mt][nt][1];
                stg[(ml + 8) * 68 + nl]     = acc[mt][nt][2];
                stg[(ml + 8) * 68 + nl + 1] = acc[mt][nt][3];
            }
        __syncthreads();
        for (int i = tid; i < 64 * 32; i += THREADS) {
            int row = i >> 5, sl = i & 31;
            int b = m0 + row;
            int s = (n0 >> 1) + sl;           // n0 = sb*64 -> s0 = sb*32
            float mean = stg[row * 68 + sl] + biasOut[s];
            float raw  = stg[row * 68 + 32 + sl] + biasOut[S + s];
            float sp = fmaxf(raw, 0.f) + log1pf(expf(-fabsf(raw)));
            float sd = sp + 0.1f;
            float eps = noiseSrc[(size_t)b * T * S + (size_t)tstep * S + s];
            float st = fmaf(sd, eps, mean);
            size_t o = (size_t)b * T * S + (size_t)tstep * S + s;
            outPtr[OFF_MEAN + o]  = mean;
            outPtr[OFF_STD + o]   = sd;
            outPtr[OFF_STATE + o] = st;
            g_state[b * S + s] = st;
        }
        return;
    }

    #pragma unroll
    for (int mt = 0; mt < MF; mt++)
        #pragma unroll
        for (int nt = 0; nt < NF; nt++) {
            int m = m0 + wm * WTM + mt * 16 + (lane >> 2);
            int n = n0 + wn * WTN + nt * 8 + (lane & 3) * 2;
            if constexpr (EPI == 2) {
                float b0 = bias[n], b1 = bias[n + 1];
                float v00 = elu1(acc[mt][nt][0] + b0), v01 = elu1(acc[mt][nt][1] + b1);
                float v10 = elu1(acc[mt][nt][2] + b0), v11 = elu1(acc[mt][nt][3] + b1);
                __nv_bfloat16 h00 = __float2bfloat16(v00), h01 = __float2bfloat16(v01);
                __nv_bfloat16 h10 = __float2bfloat16(v10), h11 = __float2bfloat16(v11);
                __nv_bfloat162 hi0; hi0.x = h00; hi0.y = h01;
                __nv_bfloat162 hi1; hi1.x = h10; hi1.y = h11;
                __nv_bfloat162 lo0, lo1;
                lo0.x = __float2bfloat16(v00 - __bfloat162float(h00));
                lo0.y = __float2bfloat16(v01 - __bfloat162float(h01));
                lo1.x = __float2bfloat16(v10 - __bfloat162float(h10));
                lo1.y = __float2bfloat16(v11 - __bfloat162float(h11));
                *(__nv_bfloat162*)&Chi[(size_t)m * N + n] = hi0;
                *(__nv_bfloat162*)&Clo[(size_t)m * N + n] = lo0;
                *(__nv_bfloat162*)&Chi[(size_t)(m + 8) * N + n] = hi1;
                *(__nv_bfloat162*)&Clo[(size_t)(m + 8) * N + n] = lo1;
            } else {
                float b0 = bias[n], b1 = bias[n + 1];
                *(float2*)&Cf[(size_t)m * N + n] =
                    make_float2(acc[mt][nt][0] + b0, acc[mt][nt][1] + b1);
                *(float2*)&Cf[(size_t)(m + 8) * N + n] =
                    make_float2(acc[mt][nt][2] + b0, acc[mt][nt][3] + b1);
            }
        }
}

// ---------------- wrappers ----------------

// proj: x = elu([state|action_t] @ Wpr + b_proj) -> bf16 hi/lo. grid(16,8), 256 thr.
__global__ void __launch_bounds__(NTHR)
proj_k(const float* __restrict__ actions, const float* __restrict__ b_proj, int t) {
    extern __shared__ char smem[];
    gemm_tile<64, 64, 2, 4, 2, 1>(smem, nullptr, nullptr, g_Wpr_hi, g_Wpr_lo,
        b_proj, nullptr, g_x_hi, g_x_lo,
        g_state, actions, nullptr, nullptr, nullptr, t,
        blockIdx.y * 64, blockIdx.x * 64, H, KP, 0, KP);
}

// gi = x @ Wih + b_ih. 384 tiles of 64x64, 128 thr, 3 CTAs/SM.
__global__ void __launch_bounds__(128, 3)
gi_k(const float* __restrict__ b_ih) {
    extern __shared__ char smem[];
    gemm_tile<64, 64, 2, 2, 0, 0>(smem, g_x_hi, g_x_lo, g_Wih_hi, g_Wih_lo,
        b_ih, g_gi, nullptr, nullptr,
        nullptr, nullptr, nullptr, nullptr, nullptr, 0,
        blockIdx.y * 64, blockIdx.x * 64, N3, H, 0, H);
}

// combo: gh_{t+1} = belief @ Whh + b_hh (96 fat tiles) AND h1 (32 fat tiles).
__global__ void __launch_bounds__(NTHR)
combo_k(const float* __restrict__ b_hh, const float* __restrict__ b_h1) {
    extern __shared__ char smem[];
    int tk = blockIdx.x;
    if (tk < 96) {
        int mi = tk / 24, ni = tk % 24;
        gemm_tile<128, 128, 2, 4, 0, 0>(smem, g_bel_hi, g_bel_lo, g_Whh_hi, g_Whh_lo,
            b_hh, g_gh, nullptr, nullptr,
            nullptr, nullptr, nullptr, nullptr, nullptr, 0,
            mi * 128, ni * 128, N3, R, 0, R);
    } else {
        int u = tk - 96;
        int mi = u / 8, ni = u % 8;
        gemm_tile<128, 128, 2, 4, 2, 0>(smem, g_bel_hi, g_bel_lo, g_Wh1_hi, g_Wh1_lo,
            b_h1, nullptr, g_h_hi, g_h_lo,
            nullptr, nullptr, nullptr, nullptr, nullptr, 0,
            mi * 128, ni * 128, H, R, 0, R);
    }
}

// gh only (prologue, t = 0)
__global__ void __launch_bounds__(NTHR)
gh0_k(const float* __restrict__ b_hh) {
    extern __shared__ char smem[];
    int tk = blockIdx.x;
    int mi = tk / 24, ni = tk % 24;
    gemm_tile<128, 128, 2, 4, 0, 0>(smem, g_bel_hi, g_bel_lo, g_Whh_hi, g_Whh_lo,
        b_hh, g_gh, nullptr, nullptr,
        nullptr, nullptr, nullptr, nullptr, nullptr, 0,
        mi * 128, ni * 128, N3, R, 0, R);
}

// fused out+epi: full-K GEMM on PERMUTED Wou (tile = matched mean/raw pairs),
// epilogue does softplus + reparam sample + writes outputs and next state.
// grid(4, 8): ni = s-block of 32, mi = b-block of 64.
__global__ void __launch_bounds__(NTHR)
outepi_k(const float* __restrict__ noise, const float* __restrict__ b_out,
         float* __restrict__ out, int t) {
    extern __shared__ char smem[];
    gemm_tile<64, 64, 2, 4, 4, 0>(smem, g_h_hi, g_h_lo, g_WouP_hi, g_WouP_lo,
        nullptr, nullptr, nullptr, nullptr,
        nullptr, nullptr, noise, b_out, out, t,
        blockIdx.y * 64, blockIdx.x * 64, NO, H, 0, H);
}

// ---------------- GRU gate + belief update ----------------
__global__ void gate_k(float* __restrict__ out, int t) {
    int idx = blockIdx.x * blockDim.x + threadIdx.x;
    if (idx >= B * R) return;
    int b = idx / R, r = idx % R;
    size_t base = (size_t)b * N3;
    float ir = g_gi[base + r],          hr = g_gh[base + r];
    float iz = g_gi[base + R + r],      hz = g_gh[base + R + r];
    float in_ = g_gi[base + 2 * R + r], hn = g_gh[base + 2 * R + r];
    float rg = 1.f / (1.f + expf(-(ir + hr)));
    float zg = 1.f / (1.f + expf(-(iz + hz)));
    float ng = tanhf(in_ + rg * hn);
    float old = g_belief[idx];
    float nb = (1.f - zg) * ng + zg * old;
    g_belief[idx] = nb;
    __nv_bfloat16 h = __float2bfloat16(nb);
    g_bel_hi[idx] = h;
    g_bel_lo[idx] = __float2bfloat16(nb - __bfloat162float(h));
    size_t o = (size_t)b * T * R + (size_t)t * R + r;
    out[OFF_BEL + o]  = nb;
    out[OFF_PREV + o] = old;
}

// ---------------- launch ----------------
extern "C" void kernel_launch(void* const* d_in, const int* in_sizes, int n_in,
                              void* d_out, int out_size) {
    const float* prior_state = (const float*)d_in[0];
    const float* belief0     = (const float*)d_in[1];
    const float* actions     = (const float*)d_in[2];
    const float* noise       = (const float*)d_in[3];
    const float* W_proj = (const float*)d_in[4];
    const float* b_proj = (const float*)d_in[5];
    const float* W_ih   = (const float*)d_in[6];
    const float* b_ih   = (const float*)d_in[7];
    const float* W_hh   = (const float*)d_in[8];
    const float* b_hh   = (const float*)d_in[9];
    const float* W_h1   = (const float*)d_in[10];
    const float* b_h1   = (const float*)d_in[11];
    const float* W_out  = (const float*)d_in[12];
    const float* b_out  = (const float*)d_in[13];
    float* out = (float*)d_out;

    __nv_bfloat16 *p_Wpr_h, *p_Wpr_l, *p_Wih_h, *p_Wih_l, *p_Whh_h, *p_Whh_l;
    __nv_bfloat16 *p_Wh1_h, *p_Wh1_l, *p_Wou_h, *p_Wou_l;
    cudaGetSymbolAddress((void**)&p_Wpr_h, g_Wpr_hi);
    cudaGetSymbolAddress((void**)&p_Wpr_l, g_Wpr_lo);
    cudaGetSymbolAddress((void**)&p_Wih_h, g_Wih_hi);
    cudaGetSymbolAddress((void**)&p_Wih_l, g_Wih_lo);
    cudaGetSymbolAddress((void**)&p_Whh_h, g_Whh_hi);
    cudaGetSymbolAddress((void**)&p_Whh_l, g_Whh_lo);
    cudaGetSymbolAddress((void**)&p_Wh1_h, g_Wh1_hi);
    cudaGetSymbolAddress((void**)&p_Wh1_l, g_Wh1_lo);
    cudaGetSymbolAddress((void**)&p_Wou_h, g_WouP_hi);
    cudaGetSymbolAddress((void**)&p_Wou_l, g_WouP_lo);

    constexpr uint32_t SMEM_BIG = 3u * 2u * (128 + 128) * 80;  // 122880
    constexpr uint32_t SMEM_SML = 3u * 2u * (64 + 64) * 80;    // 61440
    cudaFuncSetAttribute((const void*)proj_k,   cudaFuncAttributeMaxDynamicSharedMemorySize, SMEM_SML);
    cudaFuncSetAttribute((const void*)gi_k,     cudaFuncAttributeMaxDynamicSharedMemorySize, SMEM_SML);
    cudaFuncSetAttribute((const void*)combo_k,  cudaFuncAttributeMaxDynamicSharedMemorySize, SMEM_BIG);
    cudaFuncSetAttribute((const void*)gh0_k,    cudaFuncAttributeMaxDynamicSharedMemorySize, SMEM_BIG);
    cudaFuncSetAttribute((const void*)outepi_k, cudaFuncAttributeMaxDynamicSharedMemorySize, SMEM_SML);

    // one-time per replay: init recurrent state + weight split + gh_0
    init_k<<<(B * R + 255) / 256, 256>>>(prior_state, belief0);
    prep_w<<<(H * KP + 255) / 256, 256>>>(W_proj, p_Wpr_h, p_Wpr_l, KP, H);
    prep_w<<<(N3 * H + 255) / 256, 256>>>(W_ih, p_Wih_h, p_Wih_l, H, N3);
    prep_w<<<(N3 * R + 255) / 256, 256>>>(W_hh, p_Whh_h, p_Whh_l, R, N3);
    prep_w<<<(H * R + 255) / 256, 256>>>(W_h1, p_Wh1_h, p_Wh1_l, R, H);
    prep_wou<<<(NO * H + 255) / 256, 256>>>(W_out, p_Wou_h, p_Wou_l);
    gh0_k<<<96, NTHR, SMEM_BIG>>>(b_hh);

    for (int t = 0; t < T; t++) {
        // x = elu([state|action_t] @ Wpr + b_proj) (fused pack)
        proj_k<<<dim3(H / 64, B / 64), NTHR, SMEM_SML>>>(actions, b_proj, t);

        // gi = x @ Wih + b_ih  -- 384 small tiles, all-SM balanced
        gi_k<<<dim3(N3 / 64, B / 64), 128, SMEM_SML>>>(b_ih);

        // GRU gates -> new belief (+hi/lo), write beliefs + prev_beliefs
        gate_k<<<(B * R + 255) / 256, 256>>>(out, t);

        // gh_{t+1} + h1 in ONE wave (fat tiles)
        combo_k<<<128, NTHR, SMEM_BIG>>>(b_hh, b_h1);

        // fused out+epi: full-K permuted GEMM + softplus + sample + outputs
        outepi_k<<<dim3(4, B / 64), NTHR, SMEM_SML>>>(noise, b_out, out, t);
    }
}

// round 15
// speedup vs baseline: 1.1690x; 1.0945x over previous
#include <cuda_runtime.h>
#include <cuda_bf16.h>
#include <math.h>
#include <stdint.h>

// ---------------- problem constants ----------------
constexpr int B = 512, T = 64, S = 128, A = 32, H = 1024, R = 1024;
constexpr int KP = S + A;     // 160
constexpr int N3 = 3 * R;     // 3072
constexpr int NO = 2 * S;     // 256
constexpr int SK = 4;

constexpr int NTHR = 256;

constexpr size_t OFF_MEAN  = 0;
constexpr size_t OFF_STD   = OFF_MEAN  + (size_t)B * T * S;
constexpr size_t OFF_STATE = OFF_STD   + (size_t)B * T * S;
constexpr size_t OFF_BEL   = OFF_STATE + (size_t)B * T * S;
constexpr size_t OFF_PREV  = OFF_BEL   + (size_t)B * T * R;

// ---------------- device scratch ----------------
__device__ float g_gi[B * N3];
__device__ float g_gh[B * N3];
__device__ float g_belief[B * R];
__device__ float g_state [B * S];
__device__ float g_mo[SK * B * NO];

__device__ __nv_bfloat16 g_x_hi[B * H],   g_x_lo[B * H];
__device__ __nv_bfloat16 g_bel_hi[B * R], g_bel_lo[B * R];
__device__ __nv_bfloat16 g_h_hi[B * H],   g_h_lo[B * H];
__device__ __nv_bfloat16 g_Wpr_hi[H * KP], g_Wpr_lo[H * KP];
__device__ __nv_bfloat16 g_Wih_hi[N3 * H], g_Wih_lo[N3 * H];
__device__ __nv_bfloat16 g_Whh_hi[N3 * R], g_Whh_lo[N3 * R];
__device__ __nv_bfloat16 g_Wh1_hi[H * R],  g_Wh1_lo[H * R];
__device__ __nv_bfloat16 g_Wou_hi[NO * H], g_Wou_lo[NO * H];

// ---------------- portable PTX helpers (sm_80+) ----------------
__device__ __forceinline__ uint32_t smem_to_u32(const void* p) {
    uint32_t a;
    asm("{ .reg .u64 t; cvta.to.shared.u64 t, %1; cvt.u32.u64 %0, t; }" : "=r"(a) : "l"(p));
    return a;
}
__device__ __forceinline__ void cp16(uint32_t saddr, const void* gaddr) {
    asm volatile("cp.async.cg.shared.global [%0], [%1], 16;" :: "r"(saddr), "l"(gaddr) : "memory");
}
__device__ __forceinline__ void cp_commit() { asm volatile("cp.async.commit_group;" ::: "memory"); }
__device__ __forceinline__ void cp_wait1()  { asm volatile("cp.async.wait_group 1;" ::: "memory"); }

__device__ __forceinline__ void ldsm4(uint32_t a, uint32_t& r0, uint32_t& r1,
                                      uint32_t& r2, uint32_t& r3) {
    asm volatile("ldmatrix.sync.aligned.m8n8.x4.shared.b16 {%0,%1,%2,%3}, [%4];"
                 : "=r"(r0), "=r"(r1), "=r"(r2), "=r"(r3) : "r"(a));
}
__device__ __forceinline__ void mma_bf16(float* c, const uint32_t* a, const uint32_t* b) {
    asm volatile("mma.sync.aligned.m16n8k16.row.col.f32.bf16.bf16.f32 "
                 "{%0,%1,%2,%3},{%4,%5,%6,%7},{%8,%9},{%0,%1,%2,%3};"
                 : "+f"(c[0]), "+f"(c[1]), "+f"(c[2]), "+f"(c[3])
                 : "r"(a[0]), "r"(a[1]), "r"(a[2]), "r"(a[3]), "r"(b[0]), "r"(b[1]));
}
__device__ __forceinline__ float elu1(float v) { return (v > 0.f) ? v : expm1f(v); }

// ---------------- init ----------------
__global__ void init_k(const float* __restrict__ prior_state,
                       const float* __restrict__ belief0) {
    int idx = blockIdx.x * blockDim.x + threadIdx.x;
    if (idx < B * R) {
        float v = belief0[idx];
        g_belief[idx] = v;
        __nv_bfloat16 h = __float2bfloat16(v);
        g_bel_hi[idx] = h;
        g_bel_lo[idx] = __float2bfloat16(v - __bfloat162float(h));
    }
    if (idx < B * S) g_state[idx] = prior_state[idx];
}

// ---------------- weight prep: W[K][N] -> hi/lo[N][K] ----------------
__global__ void prep_w(const float* __restrict__ W, __nv_bfloat16* __restrict__ hi,
                       __nv_bfloat16* __restrict__ lo, int K, int N) {
    int idx = blockIdx.x * blockDim.x + threadIdx.x;
    if (idx >= N * K) return;
    int n = idx / K, k = idx % K;
    float v = W[(size_t)k * N + n];
    __nv_bfloat16 h = __float2bfloat16(v);
    hi[idx] = h;
    lo[idx] = __float2bfloat16(v - __bfloat162float(h));
}

// ---------------- bf16-split tensor-core GEMM tile, 3-stage pipeline ---------
template<int BM, int BN, int WRM, int WRN, int EPI, int PACKA>
__device__ __forceinline__ void gemm_tile(char* smem,
    const __nv_bfloat16* __restrict__ Ahi, const __nv_bfloat16* __restrict__ Alo,
    const __nv_bfloat16* __restrict__ Bhi, const __nv_bfloat16* __restrict__ Blo,
    const float* __restrict__ bias, float* __restrict__ Cf,
    __nv_bfloat16* __restrict__ Chi, __nv_bfloat16* __restrict__ Clo,
    const float* __restrict__ stateSrc, const float* __restrict__ actSrc, int tstep,
    int m0, int n0, int N, int K, int kz0, int KS)
{
    constexpr int THREADS = WRM * WRN * 32;
    constexpr int WTM = BM / WRM, WTN = BN / WRN;
    constexpr int MF = WTM / 16, NF = WTN / 8;
    constexpr int RS = 80;
    constexpr uint32_t OFS_AH = 0;
    constexpr uint32_t OFS_AL = (uint32_t)BM * RS;
    constexpr uint32_t OFS_BH = 2u * BM * RS;
    constexpr uint32_t OFS_BL = 2u * BM * RS + (uint32_t)BN * RS;
    constexpr uint32_t BUFSZ  = 2u * (BM + BN) * RS;

    const uint32_t sb = smem_to_u32(smem);
    const int tid = threadIdx.x;
    const int wid = tid >> 5, lane = tid & 31;
    const int wm = wid / WRN, wn = wid % WRN;

    const __nv_bfloat16* s0 = PACKA ? nullptr : Ahi + (size_t)m0 * K + kz0;
    const __nv_bfloat16* s1 = PACKA ? nullptr : Alo + (size_t)m0 * K + kz0;
    const __nv_bfloat16* s2 = Bhi + (size_t)n0 * K + kz0;
    const __nv_bfloat16* s3 = Blo + (size_t)n0 * K + kz0;

    const int NC = KS / 32;
    float acc[MF][NF][4];
    #pragma unroll
    for (int i = 0; i < MF; i++)
        #pragma unroll
        for (int j = 0; j < NF; j++)
            #pragma unroll
            for (int q = 0; q < 4; q++) acc[i][j][q] = 0.f;

    auto load_async = [&](int c, int buf) {
        uint32_t base = sb + (uint32_t)buf * BUFSZ;
        if constexpr (!PACKA) {
            constexpr int PPT = (BM + BN) * 8 / THREADS;
            #pragma unroll
            for (int i = 0; i < PPT; i++) {
                int p = tid + i * THREADS;
                const __nv_bfloat16* s;
                uint32_t ofs;
                int local;
                if (p < BM * 4)                   { s = s0; ofs = OFS_AH; local = p; }
                else if (p < 2 * BM * 4)          { s = s1; ofs = OFS_AL; local = p - BM * 4; }
                else if (p < 2 * BM * 4 + BN * 4) { s = s2; ofs = OFS_BH; local = p - 2 * BM * 4; }
                else                              { s = s3; ofs = OFS_BL; local = p - 2 * BM * 4 - BN * 4; }
                int row = local >> 2, k16 = local & 3;
                cp16(base + ofs + (uint32_t)row * RS + (uint32_t)k16 * 16,
                     s + (size_t)row * K + c * 32 + k16 * 8);
            }
        } else {
            constexpr int BPPT = BN * 8 / THREADS;
            #pragma unroll
            for (int i = 0; i < BPPT; i++) {
                int p = tid + i * THREADS;
                const __nv_bfloat16* s = (p < BN * 4) ? s2 : s3;
                uint32_t ofs = (p < BN * 4) ? OFS_BH : OFS_BL;
                int local = (p < BN * 4) ? p : p - BN * 4;
                int row = local >> 2, k16 = local & 3;
                cp16(base + ofs + (uint32_t)row * RS + (uint32_t)k16 * 16,
                     s + (size_t)row * K + c * 32 + k16 * 8);
            }
        }
    };

    auto load_A_pack = [&](int c, int buf) {
        if constexpr (PACKA) {
            char* bm = smem + (uint32_t)buf * BUFSZ;
            constexpr int APPT = BM * 4 / THREADS;
            #pragma unroll
            for (int i = 0; i < APPT; i++) {
                int slot = tid + i * THREADS;
                int row = slot >> 2, g8 = slot & 3;
                int kb = c * 32 + g8 * 8;
                __nv_bfloat16 hv[8], lv[8];
                #pragma unroll
                for (int j = 0; j < 8; j++) {
                    int col = kb + j;
                    float v = (col < S)
                        ? stateSrc[(size_t)(m0 + row) * S + col]
                        : actSrc[(size_t)(m0 + row) * T * A + (size_t)tstep * A + (col - S)];
                    __nv_bfloat16 h = __float2bfloat16(v);
                    hv[j] = h;
                    lv[j] = __float2bfloat16(v - __bfloat162float(h));
                }
                *(uint4*)(bm + OFS_AH + (uint32_t)row * RS + (uint32_t)g8 * 16) = *(uint4*)hv;
                *(uint4*)(bm + OFS_AL + (uint32_t)row * RS + (uint32_t)g8 * 16) = *(uint4*)lv;
            }
        }
    };

    auto mma_chunk = [&](int buf) {
        uint32_t base = sb + (uint32_t)buf * BUFSZ;
        const int grp = lane >> 3, l8 = lane & 7;
        #pragma unroll
        for (int ks = 0; ks < 2; ks++) {
            uint32_t ahi[MF][4], alo[MF][4], bhi[NF][2], blo[NF][2];
            uint32_t arow = (uint32_t)(wm * WTM + (grp & 1) * 8 + l8);
            uint32_t acol = (uint32_t)(ks * 32 + (grp >> 1) * 16);
            #pragma unroll
            for (int mt = 0; mt < MF; mt++) {
                uint32_t r = (arow + mt * 16) * RS + acol;
                ldsm4(base + OFS_AH + r, ahi[mt][0], ahi[mt][1], ahi[mt][2], ahi[mt][3]);
                ldsm4(base + OFS_AL + r, alo[mt][0], alo[mt][1], alo[mt][2], alo[mt][3]);
            }
            uint32_t brow = (uint32_t)(wn * WTN + (grp >> 1) * 8 + l8);
            uint32_t bcol = (uint32_t)(ks * 32 + (grp & 1) * 16);
            #pragma unroll
            for (int np = 0; np < NF / 2; np++) {
                uint32_t r = (brow + np * 16) * RS + bcol;
                ldsm4(base + OFS_BH + r, bhi[2 * np][0], bhi[2 * np][1],
                      bhi[2 * np + 1][0], bhi[2 * np + 1][1]);
                ldsm4(base + OFS_BL + r, blo[2 * np][0], blo[2 * np][1],
                      blo[2 * np + 1][0], blo[2 * np + 1][1]);
            }
            #pragma unroll
            for (int mt = 0; mt < MF; mt++)
                #pragma unroll
                for (int nt = 0; nt < NF; nt++) {
                    mma_bf16(acc[mt][nt], ahi[mt], bhi[nt]);
                    mma_bf16(acc[mt][nt], ahi[mt], blo[nt]);
                    mma_bf16(acc[mt][nt], alo[mt], bhi[nt]);
                }
        }
    };

    load_A_pack(0, 0);
    load_async(0, 0); cp_commit();
    if (NC > 1) { load_A_pack(1, 1); load_async(1, 1); }
    cp_commit();
    for (int c = 0; c < NC; c++) {
        cp_wait1();
        __syncthreads();
        mma_chunk(c % 3);
        if (c + 2 < NC) { load_A_pack(c + 2, (c + 2) % 3); load_async(c + 2, (c + 2) % 3); }
        cp_commit();
    }

    #pragma unroll
    for (int mt = 0; mt < MF; mt++)
        #pragma unroll
        for (int nt = 0; nt < NF; nt++) {
            int m = m0 + wm * WTM + mt * 16 + (lane >> 2);
            int n = n0 + wn * WTN + nt * 8 + (lane & 3) * 2;
            if constexpr (EPI == 3) {
                *(float2*)&Cf[(size_t)m * N + n] =
                    make_float2(acc[mt][nt][0], acc[mt][nt][1]);
                *(float2*)&Cf[(size_t)(m + 8) * N + n] =
                    make_float2(acc[mt][nt][2], acc[mt][nt][3]);
            } else if constexpr (EPI == 2) {
                float b0 = bias[n], b1 = bias[n + 1];
                float v00 = elu1(acc[mt][nt][0] + b0), v01 = elu1(acc[mt][nt][1] + b1);
                float v10 = elu1(acc[mt][nt][2] + b0), v11 = elu1(acc[mt][nt][3] + b1);
                __nv_bfloat16 h00 = __float2bfloat16(v00), h01 = __float2bfloat16(v01);
                __nv_bfloat16 h10 = __float2bfloat16(v10), h11 = __float2bfloat16(v11);
                __nv_bfloat162 hi0; hi0.x = h00; hi0.y = h01;
                __nv_bfloat162 hi1; hi1.x = h10; hi1.y = h11;
                __nv_bfloat162 lo0, lo1;
                lo0.x = __float2bfloat16(v00 - __bfloat162float(h00));
                lo0.y = __float2bfloat16(v01 - __bfloat162float(h01));
                lo1.x = __float2bfloat16(v10 - __bfloat162float(h10));
                lo1.y = __float2bfloat16(v11 - __bfloat162float(h11));
                *(__nv_bfloat162*)&Chi[(size_t)m * N + n] = hi0;
                *(__nv_bfloat162*)&Clo[(size_t)m * N + n] = lo0;
                *(__nv_bfloat162*)&Chi[(size_t)(m + 8) * N + n] = hi1;
                *(__nv_bfloat162*)&Clo[(size_t)(m + 8) * N + n] = lo1;
            } else {
                float b0 = bias[n], b1 = bias[n + 1];
                *(float2*)&Cf[(size_t)m * N + n] =
                    make_float2(acc[mt][nt][0] + b0, acc[mt][nt][1] + b1);
                *(float2*)&Cf[(size_t)(m + 8) * N + n] =
                    make_float2(acc[mt][nt][2] + b0, acc[mt][nt][3] + b1);
            }
        }
}

// ---------------- wrappers ----------------

// proj: x = elu([state|action_t] @ Wpr + b_proj) -> bf16 hi/lo. grid(16,8), 256 thr.
__global__ void __launch_bounds__(NTHR)
proj_k(const float* __restrict__ actions, const float* __restrict__ b_proj, int t) {
    extern __shared__ char smem[];
    gemm_tile<64, 64, 2, 4, 2, 1>(smem, nullptr, nullptr, g_Wpr_hi, g_Wpr_lo,
        b_proj, nullptr, g_x_hi, g_x_lo, g_state, actions, t,
        blockIdx.y * 64, blockIdx.x * 64, H, KP, 0, KP);
}

// gi = x @ Wih + b_ih. 384 tiles of 64x64, 128 thr, 3 CTAs/SM -> all resident.
__global__ void __launch_bounds__(128, 3)
gi_k(const float* __restrict__ b_ih) {
    extern __shared__ char smem[];
    gemm_tile<64, 64, 2, 2, 0, 0>(smem, g_x_hi, g_x_lo, g_Wih_hi, g_Wih_lo,
        b_ih, g_gi, nullptr, nullptr, nullptr, nullptr, 0,
        blockIdx.y * 64, blockIdx.x * 64, N3, H, 0, H);
}

// combo: gh_{t+1} (192 tiles 128x64) + h1 (64 tiles 128x64) = 256 CTAs,
// 128 thr, 92KB smem -> 2 CTAs/SM (304 capacity) -> single balanced wave.
__global__ void __launch_bounds__(128, 2)
combo_k(const float* __restrict__ b_hh, const float* __restrict__ b_h1) {
    extern __shared__ char smem[];
    int tk = blockIdx.x;
    if (tk < 192) {
        int mi = tk / 48, ni = tk % 48;
        gemm_tile<128, 64, 2, 2, 0, 0>(smem, g_bel_hi, g_bel_lo, g_Whh_hi, g_Whh_lo,
            b_hh, g_gh, nullptr, nullptr, nullptr, nullptr, 0,
            mi * 128, ni * 64, N3, R, 0, R);
    } else {
        int u = tk - 192;
        int mi = u / 16, ni = u % 16;
        gemm_tile<128, 64, 2, 2, 2, 0>(smem, g_bel_hi, g_bel_lo, g_Wh1_hi, g_Wh1_lo,
            b_h1, nullptr, g_h_hi, g_h_lo, nullptr, nullptr, 0,
            mi * 128, ni * 64, H, R, 0, R);
    }
}

// gh only (prologue, t = 0): 192 tiles of 128x64.
__global__ void __launch_bounds__(128, 2)
gh0_k(const float* __restrict__ b_hh) {
    extern __shared__ char smem[];
    int tk = blockIdx.x;
    int mi = tk / 48, ni = tk % 48;
    gemm_tile<128, 64, 2, 2, 0, 0>(smem, g_bel_hi, g_bel_lo, g_Whh_hi, g_Whh_lo,
        b_hh, g_gh, nullptr, nullptr, nullptr, nullptr, 0,
        mi * 128, ni * 64, N3, R, 0, R);
}

// out: [mean|raw] partials = h @ Wou over K-slice. grid(4,8,SK).
__global__ void __launch_bounds__(NTHR)
out_k() {
    extern __shared__ char smem[];
    int z = blockIdx.z;
    gemm_tile<64, 64, 2, 4, 3, 0>(smem, g_h_hi, g_h_lo, g_Wou_hi, g_Wou_lo,
        nullptr, g_mo + (size_t)z * B * NO, nullptr, nullptr, nullptr, nullptr, 0,
        blockIdx.y * 64, blockIdx.x * 64, NO, H, z * 256, 256);
}

// ---------------- GRU gate + belief update ----------------
__global__ void gate_k(float* __restrict__ out, int t) {
    int idx = blockIdx.x * blockDim.x + threadIdx.x;
    if (idx >= B * R) return;
    int b = idx / R, r = idx % R;
    size_t base = (size_t)b * N3;
    float ir = g_gi[base + r],          hr = g_gh[base + r];
    float iz = g_gi[base + R + r],      hz = g_gh[base + R + r];
    float in_ = g_gi[base + 2 * R + r], hn = g_gh[base + 2 * R + r];
    float rg = 1.f / (1.f + expf(-(ir + hr)));
    float zg = 1.f / (1.f + expf(-(iz + hz)));
    float ng = tanhf(in_ + rg * hn);
    float old = g_belief[idx];
    float nb = (1.f - zg) * ng + zg * old;
    g_belief[idx] = nb;
    __nv_bfloat16 h = __float2bfloat16(nb);
    g_bel_hi[idx] = h;
    g_bel_lo[idx] = __float2bfloat16(nb - __bfloat162float(h));
    size_t o = (size_t)b * T * R + (size_t)t * R + r;
    out[OFF_BEL + o]  = nb;
    out[OFF_PREV + o] = old;
}

// ---------------- epilogue: reduce split-K, softplus, sample ----------------
__global__ void epi_k(const float* __restrict__ noise,
                      const float* __restrict__ b_out,
                      float* __restrict__ out, int t) {
    int idx = blockIdx.x * blockDim.x + threadIdx.x;
    if (idx >= B * S) return;
    int b = idx / S, s = idx % S;
    float mean = b_out[s];
    float raw  = b_out[S + s];
    #pragma unroll
    for (int z = 0; z < SK; z++) {
        mean += g_mo[(size_t)z * B * NO + (size_t)b * NO + s];
        raw  += g_mo[(size_t)z * B * NO + (size_t)b * NO + S + s];
    }
    float sp  = fmaxf(raw, 0.f) + log1pf(expf(-fabsf(raw)));
    float std = sp + 0.1f;
    float eps = noise[(size_t)b * T * S + (size_t)t * S + s];
    float st  = fmaf(std, eps, mean);
    size_t o = (size_t)b * T * S + (size_t)t * S + s;
    out[OFF_MEAN + o]  = mean;
    out[OFF_STD + o]   = std;
    out[OFF_STATE + o] = st;
    g_state[idx] = st;
}

// ---------------- launch ----------------
extern "C" void kernel_launch(void* const* d_in, const int* in_sizes, int n_in,
                              void* d_out, int out_size) {
    const float* prior_state = (const float*)d_in[0];
    const float* belief0     = (const float*)d_in[1];
    const float* actions     = (const float*)d_in[2];
    const float* noise       = (const float*)d_in[3];
    const float* W_proj = (const float*)d_in[4];
    const float* b_proj = (const float*)d_in[5];
    const float* W_ih   = (const float*)d_in[6];
    const float* b_ih   = (const float*)d_in[7];
    const float* W_hh   = (const float*)d_in[8];
    const float* b_hh   = (const float*)d_in[9];
    const float* W_h1   = (const float*)d_in[10];
    const float* b_h1   = (const float*)d_in[11];
    const float* W_out  = (const float*)d_in[12];
    const float* b_out  = (const float*)d_in[13];
    float* out = (float*)d_out;

    __nv_bfloat16 *p_Wpr_h, *p_Wpr_l, *p_Wih_h, *p_Wih_l, *p_Whh_h, *p_Whh_l;
    __nv_bfloat16 *p_Wh1_h, *p_Wh1_l, *p_Wou_h, *p_Wou_l;
    cudaGetSymbolAddress((void**)&p_Wpr_h, g_Wpr_hi);
    cudaGetSymbolAddress((void**)&p_Wpr_l, g_Wpr_lo);
    cudaGetSymbolAddress((void**)&p_Wih_h, g_Wih_hi);
    cudaGetSymbolAddress((void**)&p_Wih_l, g_Wih_lo);
    cudaGetSymbolAddress((void**)&p_Whh_h, g_Whh_hi);
    cudaGetSymbolAddress((void**)&p_Whh_l, g_Whh_lo);
    cudaGetSymbolAddress((void**)&p_Wh1_h, g_Wh1_hi);
    cudaGetSymbolAddress((void**)&p_Wh1_l, g_Wh1_lo);
    cudaGetSymbolAddress((void**)&p_Wou_h, g_Wou_hi);
    cudaGetSymbolAddress((void**)&p_Wou_l, g_Wou_lo);

    constexpr uint32_t SMEM_SML = 3u * 2u * (64 + 64) * 80;    // 61440
    constexpr uint32_t SMEM_MED = 3u * 2u * (128 + 64) * 80;   // 92160
    cudaFuncSetAttribute((const void*)proj_k,  cudaFuncAttributeMaxDynamicSharedMemorySize, SMEM_SML);
    cudaFuncSetAttribute((const void*)gi_k,    cudaFuncAttributeMaxDynamicSharedMemorySize, SMEM_SML);
    cudaFuncSetAttribute((const void*)combo_k, cudaFuncAttributeMaxDynamicSharedMemorySize, SMEM_MED);
    cudaFuncSetAttribute((const void*)gh0_k,   cudaFuncAttributeMaxDynamicSharedMemorySize, SMEM_MED);
    cudaFuncSetAttribute((const void*)out_k,   cudaFuncAttributeMaxDynamicSharedMemorySize, SMEM_SML);

    // one-time per replay: init recurrent state + weight split + gh_0
    init_k<<<(B * R + 255) / 256, 256>>>(prior_state, belief0);
    prep_w<<<(H * KP + 255) / 256, 256>>>(W_proj, p_Wpr_h, p_Wpr_l, KP, H);
    prep_w<<<(N3 * H + 255) / 256, 256>>>(W_ih, p_Wih_h, p_Wih_l, H, N3);
    prep_w<<<(N3 * R + 255) / 256, 256>>>(W_hh, p_Whh_h, p_Whh_l, R, N3);
    prep_w<<<(H * R + 255) / 256, 256>>>(W_h1, p_Wh1_h, p_Wh1_l, R, H);
    prep_w<<<(NO * H + 255) / 256, 256>>>(W_out, p_Wou_h, p_Wou_l, H, NO);
    gh0_k<<<192, 128, SMEM_MED>>>(b_hh);

    for (int t = 0; t < T; t++) {
        // x = elu([state|action_t] @ Wpr + b_proj) (fused pack)
        proj_k<<<dim3(H / 64, B / 64), NTHR, SMEM_SML>>>(actions, b_proj, t);

        // gi = x @ Wih + b_ih  -- 384 small tiles, all-SM balanced
        gi_k<<<dim3(N3 / 64, B / 64), 128, SMEM_SML>>>(b_ih);

        // GRU gates -> new belief (+hi/lo), write beliefs + prev_beliefs
        gate_k<<<(B * R + 255) / 256, 256>>>(out, t);

        // gh_{t+1} + h1 -- 256 medium tiles, 2 CTAs/SM, single wave
        combo_k<<<256, 128, SMEM_MED>>>(b_hh, b_h1);

        // [mean|raw] partials = h @ Wou (split-K=4)
        out_k<<<dim3(NO / 64, B / 64, SK), NTHR, SMEM_SML>>>();

        // reduce + bias, softplus, reparam sample
        epi_k<<<(B * S + 255) / 256, 256>>>(noise, b_out, out, t);
    }
}

// round 16
// speedup vs baseline: 1.2055x; 1.0312x over previous
#include <cuda_runtime.h>
#include <cuda_bf16.h>
#include <math.h>
#include <stdint.h>

// ---------------- problem constants ----------------
constexpr int B = 512, T = 64, S = 128, A = 32, H = 1024, R = 1024;
constexpr int KP = S + A;     // 160
constexpr int N3 = 3 * R;     // 3072
constexpr int NO = 2 * S;     // 256
constexpr int SK = 8;         // split-K for out GEMM (K-slice = 128)

constexpr int NTHR = 256;

constexpr size_t OFF_MEAN  = 0;
constexpr size_t OFF_STD   = OFF_MEAN  + (size_t)B * T * S;
constexpr size_t OFF_STATE = OFF_STD   + (size_t)B * T * S;
constexpr size_t OFF_BEL   = OFF_STATE + (size_t)B * T * S;
constexpr size_t OFF_PREV  = OFF_BEL   + (size_t)B * T * R;

// ---------------- device scratch ----------------
__device__ float g_gi[B * N3];
__device__ float g_gh[B * N3];
__device__ float g_belief[B * R];
__device__ float g_state [B * S];
__device__ float g_mo[SK * B * NO];

__device__ __nv_bfloat16 g_x_hi[B * H],   g_x_lo[B * H];
__device__ __nv_bfloat16 g_bel_hi[B * R], g_bel_lo[B * R];
__device__ __nv_bfloat16 g_h_hi[B * H],   g_h_lo[B * H];
__device__ __nv_bfloat16 g_Wpr_hi[H * KP], g_Wpr_lo[H * KP];
__device__ __nv_bfloat16 g_Wih_hi[N3 * H], g_Wih_lo[N3 * H];
__device__ __nv_bfloat16 g_Whh_hi[N3 * R], g_Whh_lo[N3 * R];
__device__ __nv_bfloat16 g_Wh1_hi[H * R],  g_Wh1_lo[H * R];
__device__ __nv_bfloat16 g_Wou_hi[NO * H], g_Wou_lo[NO * H];

// ---------------- portable PTX helpers (sm_80+) ----------------
__device__ __forceinline__ uint32_t smem_to_u32(const void* p) {
    uint32_t a;
    asm("{ .reg .u64 t; cvta.to.shared.u64 t, %1; cvt.u32.u64 %0, t; }" : "=r"(a) : "l"(p));
    return a;
}
__device__ __forceinline__ void cp16(uint32_t saddr, const void* gaddr) {
    asm volatile("cp.async.cg.shared.global [%0], [%1], 16;" :: "r"(saddr), "l"(gaddr) : "memory");
}
__device__ __forceinline__ void cp_commit() { asm volatile("cp.async.commit_group;" ::: "memory"); }
__device__ __forceinline__ void cp_wait1()  { asm volatile("cp.async.wait_group 1;" ::: "memory"); }

__device__ __forceinline__ void ldsm4(uint32_t a, uint32_t& r0, uint32_t& r1,
                                      uint32_t& r2, uint32_t& r3) {
    asm volatile("ldmatrix.sync.aligned.m8n8.x4.shared.b16 {%0,%1,%2,%3}, [%4];"
                 : "=r"(r0), "=r"(r1), "=r"(r2), "=r"(r3) : "r"(a));
}
__device__ __forceinline__ void mma_bf16(float* c, const uint32_t* a, const uint32_t* b) {
    asm volatile("mma.sync.aligned.m16n8k16.row.col.f32.bf16.bf16.f32 "
                 "{%0,%1,%2,%3},{%4,%5,%6,%7},{%8,%9},{%0,%1,%2,%3};"
                 : "+f"(c[0]), "+f"(c[1]), "+f"(c[2]), "+f"(c[3])
                 : "r"(a[0]), "r"(a[1]), "r"(a[2]), "r"(a[3]), "r"(b[0]), "r"(b[1]));
}
__device__ __forceinline__ float elu1(float v) { return (v > 0.f) ? v : expm1f(v); }

// ---------------- init ----------------
__global__ void init_k(const float* __restrict__ prior_state,
                       const float* __restrict__ belief0) {
    int idx = blockIdx.x * blockDim.x + threadIdx.x;
    if (idx < B * R) {
        float v = belief0[idx];
        g_belief[idx] = v;
        __nv_bfloat16 h = __float2bfloat16(v);
        g_bel_hi[idx] = h;
        g_bel_lo[idx] = __float2bfloat16(v - __bfloat162float(h));
    }
    if (idx < B * S) g_state[idx] = prior_state[idx];
}

// ---------------- weight prep: W[K][N] -> hi/lo[N][K] ----------------
__global__ void prep_w(const float* __restrict__ W, __nv_bfloat16* __restrict__ hi,
                       __nv_bfloat16* __restrict__ lo, int K, int N) {
    int idx = blockIdx.x * blockDim.x + threadIdx.x;
    if (idx >= N * K) return;
    int n = idx / K, k = idx % K;
    float v = W[(size_t)k * N + n];
    __nv_bfloat16 h = __float2bfloat16(v);
    hi[idx] = h;
    lo[idx] = __float2bfloat16(v - __bfloat162float(h));
}

// ---------------- bf16-split tensor-core GEMM tile, 3-stage pipeline ---------
template<int BM, int BN, int WRM, int WRN, int EPI, int PACKA>
__device__ __forceinline__ void gemm_tile(char* smem,
    const __nv_bfloat16* __restrict__ Ahi, const __nv_bfloat16* __restrict__ Alo,
    const __nv_bfloat16* __restrict__ Bhi, const __nv_bfloat16* __restrict__ Blo,
    const float* __restrict__ bias, float* __restrict__ Cf,
    __nv_bfloat16* __restrict__ Chi, __nv_bfloat16* __restrict__ Clo,
    const float* __restrict__ stateSrc, const float* __restrict__ actSrc, int tstep,
    int m0, int n0, int N, int K, int kz0, int KS)
{
    constexpr int THREADS = WRM * WRN * 32;
    constexpr int WTM = BM / WRM, WTN = BN / WRN;
    constexpr int MF = WTM / 16, NF = WTN / 8;
    constexpr int RS = 80;
    constexpr uint32_t OFS_AH = 0;
    constexpr uint32_t OFS_AL = (uint32_t)BM * RS;
    constexpr uint32_t OFS_BH = 2u * BM * RS;
    constexpr uint32_t OFS_BL = 2u * BM * RS + (uint32_t)BN * RS;
    constexpr uint32_t BUFSZ  = 2u * (BM + BN) * RS;

    const uint32_t sb = smem_to_u32(smem);
    const int tid = threadIdx.x;
    const int wid = tid >> 5, lane = tid & 31;
    const int wm = wid / WRN, wn = wid % WRN;

    const __nv_bfloat16* s0 = PACKA ? nullptr : Ahi + (size_t)m0 * K + kz0;
    const __nv_bfloat16* s1 = PACKA ? nullptr : Alo + (size_t)m0 * K + kz0;
    const __nv_bfloat16* s2 = Bhi + (size_t)n0 * K + kz0;
    const __nv_bfloat16* s3 = Blo + (size_t)n0 * K + kz0;

    const int NC = KS / 32;
    float acc[MF][NF][4];
    #pragma unroll
    for (int i = 0; i < MF; i++)
        #pragma unroll
        for (int j = 0; j < NF; j++)
            #pragma unroll
            for (int q = 0; q < 4; q++) acc[i][j][q] = 0.f;

    auto load_async = [&](int c, int buf) {
        uint32_t base = sb + (uint32_t)buf * BUFSZ;
        if constexpr (!PACKA) {
            constexpr int PPT = (BM + BN) * 8 / THREADS;
            #pragma unroll
            for (int i = 0; i < PPT; i++) {
                int p = tid + i * THREADS;
                const __nv_bfloat16* s;
                uint32_t ofs;
                int local;
                if (p < BM * 4)                   { s = s0; ofs = OFS_AH; local = p; }
                else if (p < 2 * BM * 4)          { s = s1; ofs = OFS_AL; local = p - BM * 4; }
                else if (p < 2 * BM * 4 + BN * 4) { s = s2; ofs = OFS_BH; local = p - 2 * BM * 4; }
                else                              { s = s3; ofs = OFS_BL; local = p - 2 * BM * 4 - BN * 4; }
                int row = local >> 2, k16 = local & 3;
                cp16(base + ofs + (uint32_t)row * RS + (uint32_t)k16 * 16,
                     s + (size_t)row * K + c * 32 + k16 * 8);
            }
        } else {
            constexpr int BPPT = BN * 8 / THREADS;
            #pragma unroll
            for (int i = 0; i < BPPT; i++) {
                int p = tid + i * THREADS;
                const __nv_bfloat16* s = (p < BN * 4) ? s2 : s3;
                uint32_t ofs = (p < BN * 4) ? OFS_BH : OFS_BL;
                int local = (p < BN * 4) ? p : p - BN * 4;
                int row = local >> 2, k16 = local & 3;
                cp16(base + ofs + (uint32_t)row * RS + (uint32_t)k16 * 16,
                     s + (size_t)row * K + c * 32 + k16 * 8);
            }
        }
    };

    auto load_A_pack = [&](int c, int buf) {
        if constexpr (PACKA) {
            char* bm = smem + (uint32_t)buf * BUFSZ;
            constexpr int APPT = BM * 4 / THREADS;
            #pragma unroll
            for (int i = 0; i < APPT; i++) {
                int slot = tid + i * THREADS;
                int row = slot >> 2, g8 = slot & 3;
                int kb = c * 32 + g8 * 8;
                __nv_bfloat16 hv[8], lv[8];
                #pragma unroll
                for (int j = 0; j < 8; j++) {
                    int col = kb + j;
                    float v = (col < S)
                        ? stateSrc[(size_t)(m0 + row) * S + col]
                        : actSrc[(size_t)(m0 + row) * T * A + (size_t)tstep * A + (col - S)];
                    __nv_bfloat16 h = __float2bfloat16(v);
                    hv[j] = h;
                    lv[j] = __float2bfloat16(v - __bfloat162float(h));
                }
                *(uint4*)(bm + OFS_AH + (uint32_t)row * RS + (uint32_t)g8 * 16) = *(uint4*)hv;
                *(uint4*)(bm + OFS_AL + (uint32_t)row * RS + (uint32_t)g8 * 16) = *(uint4*)lv;
            }
        }
    };

    auto mma_chunk = [&](int buf) {
        uint32_t base = sb + (uint32_t)buf * BUFSZ;
        const int grp = lane >> 3, l8 = lane & 7;
        #pragma unroll
        for (int ks = 0; ks < 2; ks++) {
            uint32_t ahi[MF][4], alo[MF][4], bhi[NF][2], blo[NF][2];
            uint32_t arow = (uint32_t)(wm * WTM + (grp & 1) * 8 + l8);
            uint32_t acol = (uint32_t)(ks * 32 + (grp >> 1) * 16);
            #pragma unroll
            for (int mt = 0; mt < MF; mt++) {
                uint32_t r = (arow + mt * 16) * RS + acol;
                ldsm4(base + OFS_AH + r, ahi[mt][0], ahi[mt][1], ahi[mt][2], ahi[mt][3]);
                ldsm4(base + OFS_AL + r, alo[mt][0], alo[mt][1], alo[mt][2], alo[mt][3]);
            }
            uint32_t brow = (uint32_t)(wn * WTN + (grp >> 1) * 8 + l8);
            uint32_t bcol = (uint32_t)(ks * 32 + (grp & 1) * 16);
            #pragma unroll
            for (int np = 0; np < NF / 2; np++) {
                uint32_t r = (brow + np * 16) * RS + bcol;
                ldsm4(base + OFS_BH + r, bhi[2 * np][0], bhi[2 * np][1],
                      bhi[2 * np + 1][0], bhi[2 * np + 1][1]);
                ldsm4(base + OFS_BL + r, blo[2 * np][0], blo[2 * np][1],
                      blo[2 * np + 1][0], blo[2 * np + 1][1]);
            }
            #pragma unroll
            for (int mt = 0; mt < MF; mt++)
                #pragma unroll
                for (int nt = 0; nt < NF; nt++) {
                    mma_bf16(acc[mt][nt], ahi[mt], bhi[nt]);
                    mma_bf16(acc[mt][nt], ahi[mt], blo[nt]);
                    mma_bf16(acc[mt][nt], alo[mt], bhi[nt]);
                }
        }
    };

    load_A_pack(0, 0);
    load_async(0, 0); cp_commit();
    if (NC > 1) { load_A_pack(1, 1); load_async(1, 1); }
    cp_commit();
    for (int c = 0; c < NC; c++) {
        cp_wait1();
        __syncthreads();
        mma_chunk(c % 3);
        if (c + 2 < NC) { load_A_pack(c + 2, (c + 2) % 3); load_async(c + 2, (c + 2) % 3); }
        cp_commit();
    }

    #pragma unroll
    for (int mt = 0; mt < MF; mt++)
        #pragma unroll
        for (int nt = 0; nt < NF; nt++) {
            int m = m0 + wm * WTM + mt * 16 + (lane >> 2);
            int n = n0 + wn * WTN + nt * 8 + (lane & 3) * 2;
            if constexpr (EPI == 3) {
                *(float2*)&Cf[(size_t)m * N + n] =
                    make_float2(acc[mt][nt][0], acc[mt][nt][1]);
                *(float2*)&Cf[(size_t)(m + 8) * N + n] =
                    make_float2(acc[mt][nt][2], acc[mt][nt][3]);
            } else if constexpr (EPI == 2) {
                float b0 = bias[n], b1 = bias[n + 1];
                float v00 = elu1(acc[mt][nt][0] + b0), v01 = elu1(acc[mt][nt][1] + b1);
                float v10 = elu1(acc[mt][nt][2] + b0), v11 = elu1(acc[mt][nt][3] + b1);
                __nv_bfloat16 h00 = __float2bfloat16(v00), h01 = __float2bfloat16(v01);
                __nv_bfloat16 h10 = __float2bfloat16(v10), h11 = __float2bfloat16(v11);
                __nv_bfloat162 hi0; hi0.x = h00; hi0.y = h01;
                __nv_bfloat162 hi1; hi1.x = h10; hi1.y = h11;
                __nv_bfloat162 lo0, lo1;
                lo0.x = __float2bfloat16(v00 - __bfloat162float(h00));
                lo0.y = __float2bfloat16(v01 - __bfloat162float(h01));
                lo1.x = __float2bfloat16(v10 - __bfloat162float(h10));
                lo1.y = __float2bfloat16(v11 - __bfloat162float(h11));
                *(__nv_bfloat162*)&Chi[(size_t)m * N + n] = hi0;
                *(__nv_bfloat162*)&Clo[(size_t)m * N + n] = lo0;
                *(__nv_bfloat162*)&Chi[(size_t)(m + 8) * N + n] = hi1;
                *(__nv_bfloat162*)&Clo[(size_t)(m + 8) * N + n] = lo1;
            } else {
                float b0 = bias[n], b1 = bias[n + 1];
                *(float2*)&Cf[(size_t)m * N + n] =
                    make_float2(acc[mt][nt][0] + b0, acc[mt][nt][1] + b1);
                *(float2*)&Cf[(size_t)(m + 8) * N + n] =
                    make_float2(acc[mt][nt][2] + b0, acc[mt][nt][3] + b1);
            }
        }
}

// ---------------- wrappers ----------------

// proj: x = elu([state|action_t] @ Wpr + b_proj) -> bf16 hi/lo. grid(16,8), 256 thr.
__global__ void __launch_bounds__(NTHR)
proj_k(const float* __restrict__ actions, const float* __restrict__ b_proj, int t) {
    extern __shared__ char smem[];
    gemm_tile<64, 64, 2, 4, 2, 1>(smem, nullptr, nullptr, g_Wpr_hi, g_Wpr_lo,
        b_proj, nullptr, g_x_hi, g_x_lo, g_state, actions, t,
        blockIdx.y * 64, blockIdx.x * 64, H, KP, 0, KP);
}

// gi = x @ Wih + b_ih. 384 tiles of 64x64, 128 thr, 3 CTAs/SM -> all resident.
__global__ void __launch_bounds__(128, 3)
gi_k(const float* __restrict__ b_ih) {
    extern __shared__ char smem[];
    gemm_tile<64, 64, 2, 2, 0, 0>(smem, g_x_hi, g_x_lo, g_Wih_hi, g_Wih_lo,
        b_ih, g_gi, nullptr, nullptr, nullptr, nullptr, 0,
        blockIdx.y * 64, blockIdx.x * 64, N3, H, 0, H);
}

// combo: gh_{t+1} (96 fat tiles 128x128) + h1 (32 fat tiles) = 128 CTAs, 1 wave.
__global__ void __launch_bounds__(NTHR)
combo_k(const float* __restrict__ b_hh, const float* __restrict__ b_h1) {
    extern __shared__ char smem[];
    int tk = blockIdx.x;
    if (tk < 96) {
        int mi = tk / 24, ni = tk % 24;
        gemm_tile<128, 128, 2, 4, 0, 0>(smem, g_bel_hi, g_bel_lo, g_Whh_hi, g_Whh_lo,
            b_hh, g_gh, nullptr, nullptr, nullptr, nullptr, 0,
            mi * 128, ni * 128, N3, R, 0, R);
    } else {
        int u = tk - 96;
        int mi = u / 8, ni = u % 8;
        gemm_tile<128, 128, 2, 4, 2, 0>(smem, g_bel_hi, g_bel_lo, g_Wh1_hi, g_Wh1_lo,
            b_h1, nullptr, g_h_hi, g_h_lo, nullptr, nullptr, 0,
            mi * 128, ni * 128, H, R, 0, R);
    }
}

// gh only (prologue, t = 0)
__global__ void __launch_bounds__(NTHR)
gh0_k(const float* __restrict__ b_hh) {
    extern __shared__ char smem[];
    int tk = blockIdx.x;
    int mi = tk / 24, ni = tk % 24;
    gemm_tile<128, 128, 2, 4, 0, 0>(smem, g_bel_hi, g_bel_lo, g_Whh_hi, g_Whh_lo,
        b_hh, g_gh, nullptr, nullptr, nullptr, nullptr, 0,
        mi * 128, ni * 128, N3, R, 0, R);
}

// out: [mean|raw] partials = h @ Wou over K-slice of 128. grid(4,8,SK=8).
__global__ void __launch_bounds__(NTHR)
out_k() {
    extern __shared__ char smem[];
    int z = blockIdx.z;
    gemm_tile<64, 64, 2, 4, 3, 0>(smem, g_h_hi, g_h_lo, g_Wou_hi, g_Wou_lo,
        nullptr, g_mo + (size_t)z * B * NO, nullptr, nullptr, nullptr, nullptr, 0,
        blockIdx.y * 64, blockIdx.x * 64, NO, H, z * (H / SK), H / SK);
}

// ---------------- GRU gate + belief update (float4 vectorized) ----------------
__global__ void gate_k(float* __restrict__ out, int t) {
    int idx4 = blockIdx.x * blockDim.x + threadIdx.x;
    if (idx4 >= B * R / 4) return;
    int b = idx4 / (R / 4);
    int r = (idx4 % (R / 4)) * 4;
    size_t base = (size_t)b * N3;
    float4 ir = *(const float4*)&g_gi[base + r];
    float4 iz = *(const float4*)&g_gi[base + R + r];
    float4 in_ = *(const float4*)&g_gi[base + 2 * R + r];
    float4 hr = *(const float4*)&g_gh[base + r];
    float4 hz = *(const float4*)&g_gh[base + R + r];
    float4 hn = *(const float4*)&g_gh[base + 2 * R + r];
    float4 old = *(const float4*)&g_belief[b * R + r];

    float nb[4], ov[4] = {old.x, old.y, old.z, old.w};
    float irv[4] = {ir.x, ir.y, ir.z, ir.w}, izv[4] = {iz.x, iz.y, iz.z, iz.w};
    float inv[4] = {in_.x, in_.y, in_.z, in_.w};
    float hrv[4] = {hr.x, hr.y, hr.z, hr.w}, hzv[4] = {hz.x, hz.y, hz.z, hz.w};
    float hnv[4] = {hn.x, hn.y, hn.z, hn.w};
    #pragma unroll
    for (int j = 0; j < 4; j++) {
        float rg = 1.f / (1.f + expf(-(irv[j] + hrv[j])));
        float zg = 1.f / (1.f + expf(-(izv[j] + hzv[j])));
        float ng = tanhf(inv[j] + rg * hnv[j]);
        nb[j] = (1.f - zg) * ng + zg * ov[j];
    }
    *(float4*)&g_belief[b * R + r] = make_float4(nb[0], nb[1], nb[2], nb[3]);

    __nv_bfloat162 h01, h23, l01, l23;
    h01.x = __float2bfloat16(nb[0]); h01.y = __float2bfloat16(nb[1]);
    h23.x = __float2bfloat16(nb[2]); h23.y = __float2bfloat16(nb[3]);
    l01.x = __float2bfloat16(nb[0] - __bfloat162float(h01.x));
    l01.y = __float2bfloat16(nb[1] - __bfloat162float(h01.y));
    l23.x = __float2bfloat16(nb[2] - __bfloat162float(h23.x));
    l23.y = __float2bfloat16(nb[3] - __bfloat162float(h23.y));
    *(__nv_bfloat162*)&g_bel_hi[b * R + r]     = h01;
    *(__nv_bfloat162*)&g_bel_hi[b * R + r + 2] = h23;
    *(__nv_bfloat162*)&g_bel_lo[b * R + r]     = l01;
    *(__nv_bfloat162*)&g_bel_lo[b * R + r + 2] = l23;

    size_t o = (size_t)b * T * R + (size_t)t * R + r;
    *(float4*)&out[OFF_BEL + o]  = make_float4(nb[0], nb[1], nb[2], nb[3]);
    *(float4*)&out[OFF_PREV + o] = old;
}

// ---------------- epilogue: reduce split-K, softplus, sample (float4) --------
__global__ void epi_k(const float* __restrict__ noise,
                      const float* __restrict__ b_out,
                      float* __restrict__ out, int t) {
    int idx4 = blockIdx.x * blockDim.x + threadIdx.x;
    if (idx4 >= B * S / 4) return;
    int b = idx4 / (S / 4);
    int s = (idx4 % (S / 4)) * 4;
    float4 mean = *(const float4*)&b_out[s];
    float4 raw  = *(const float4*)&b_out[S + s];
    float mv[4] = {mean.x, mean.y, mean.z, mean.w};
    float rv[4] = {raw.x, raw.y, raw.z, raw.w};
    #pragma unroll
    for (int z = 0; z < SK; z++) {
        const float* p = &g_mo[(size_t)z * B * NO + (size_t)b * NO];
        float4 pm = *(const float4*)&p[s];
        float4 pr = *(const float4*)&p[S + s];
        mv[0] += pm.x; mv[1] += pm.y; mv[2] += pm.z; mv[3] += pm.w;
        rv[0] += pr.x; rv[1] += pr.y; rv[2] += pr.z; rv[3] += pr.w;
    }
    float4 eps = *(const float4*)&noise[(size_t)b * T * S + (size_t)t * S + s];
    float ev[4] = {eps.x, eps.y, eps.z, eps.w};
    float sdv[4], stv[4];
    #pragma unroll
    for (int j = 0; j < 4; j++) {
        float sp = fmaxf(rv[j], 0.f) + log1pf(expf(-fabsf(rv[j])));
        sdv[j] = sp + 0.1f;
        stv[j] = fmaf(sdv[j], ev[j], mv[j]);
    }
    size_t o = (size_t)b * T * S + (size_t)t * S + s;
    *(float4*)&out[OFF_MEAN + o]  = make_float4(mv[0], mv[1], mv[2], mv[3]);
    *(float4*)&out[OFF_STD + o]   = make_float4(sdv[0], sdv[1], sdv[2], sdv[3]);
    *(float4*)&out[OFF_STATE + o] = make_float4(stv[0], stv[1], stv[2], stv[3]);
    *(float4*)&g_state[b * S + s] = make_float4(stv[0], stv[1], stv[2], stv[3]);
}

// ---------------- launch ----------------
extern "C" void kernel_launch(void* const* d_in, const int* in_sizes, int n_in,
                              void* d_out, int out_size) {
    const float* prior_state = (const float*)d_in[0];
    const float* belief0     = (const float*)d_in[1];
    const float* actions     = (const float*)d_in[2];
    const float* noise       = (const float*)d_in[3];
    const float* W_proj = (const float*)d_in[4];
    const float* b_proj = (const float*)d_in[5];
    const float* W_ih   = (const float*)d_in[6];
    const float* b_ih   = (const float*)d_in[7];
    const float* W_hh   = (const float*)d_in[8];
    const float* b_hh   = (const float*)d_in[9];
    const float* W_h1   = (const float*)d_in[10];
    const float* b_h1   = (const float*)d_in[11];
    const float* W_out  = (const float*)d_in[12];
    const float* b_out  = (const float*)d_in[13];
    float* out = (float*)d_out;

    __nv_bfloat16 *p_Wpr_h, *p_Wpr_l, *p_Wih_h, *p_Wih_l, *p_Whh_h, *p_Whh_l;
    __nv_bfloat16 *p_Wh1_h, *p_Wh1_l, *p_Wou_h, *p_Wou_l;
    cudaGetSymbolAddress((void**)&p_Wpr_h, g_Wpr_hi);
    cudaGetSymbolAddress((void**)&p_Wpr_l, g_Wpr_lo);
    cudaGetSymbolAddress((void**)&p_Wih_h, g_Wih_hi);
    cudaGetSymbolAddress((void**)&p_Wih_l, g_Wih_lo);
    cudaGetSymbolAddress((void**)&p_Whh_h, g_Whh_hi);
    cudaGetSymbolAddress((void**)&p_Whh_l, g_Whh_lo);
    cudaGetSymbolAddress((void**)&p_Wh1_h, g_Wh1_hi);
    cudaGetSymbolAddress((void**)&p_Wh1_l, g_Wh1_lo);
    cudaGetSymbolAddress((void**)&p_Wou_h, g_Wou_hi);
    cudaGetSymbolAddress((void**)&p_Wou_l, g_Wou_lo);

    constexpr uint32_t SMEM_BIG = 3u * 2u * (128 + 128) * 80;  // 122880
    constexpr uint32_t SMEM_SML = 3u * 2u * (64 + 64) * 80;    // 61440
    cudaFuncSetAttribute((const void*)proj_k,  cudaFuncAttributeMaxDynamicSharedMemorySize, SMEM_SML);
    cudaFuncSetAttribute((const void*)gi_k,    cudaFuncAttributeMaxDynamicSharedMemorySize, SMEM_SML);
    cudaFuncSetAttribute((const void*)combo_k, cudaFuncAttributeMaxDynamicSharedMemorySize, SMEM_BIG);
    cudaFuncSetAttribute((const void*)gh0_k,   cudaFuncAttributeMaxDynamicSharedMemorySize, SMEM_BIG);
    cudaFuncSetAttribute((const void*)out_k,   cudaFuncAttributeMaxDynamicSharedMemorySize, SMEM_SML);

    // one-time per replay: init recurrent state + weight split + gh_0
    init_k<<<(B * R + 255) / 256, 256>>>(prior_state, belief0);
    prep_w<<<(H * KP + 255) / 256, 256>>>(W_proj, p_Wpr_h, p_Wpr_l, KP, H);
    prep_w<<<(N3 * H + 255) / 256, 256>>>(W_ih, p_Wih_h, p_Wih_l, H, N3);
    prep_w<<<(N3 * R + 255) / 256, 256>>>(W_hh, p_Whh_h, p_Whh_l, R, N3);
    prep_w<<<(H * R + 255) / 256, 256>>>(W_h1, p_Wh1_h, p_Wh1_l, R, H);
    prep_w<<<(NO * H + 255) / 256, 256>>>(W_out, p_Wou_h, p_Wou_l, H, NO);
    gh0_k<<<96, NTHR, SMEM_BIG>>>(b_hh);

    for (int t = 0; t < T; t++) {
        // x = elu([state|action_t] @ Wpr + b_proj) (fused pack)
        proj_k<<<dim3(H / 64, B / 64), NTHR, SMEM_SML>>>(actions, b_proj, t);

        // gi = x @ Wih + b_ih  -- 384 small tiles, all-SM balanced
        gi_k<<<dim3(N3 / 64, B / 64), 128, SMEM_SML>>>(b_ih);

        // GRU gates -> new belief (+hi/lo), write beliefs + prev_beliefs
        gate_k<<<(B * R / 4 + 255) / 256, 256>>>(out, t);

        // gh_{t+1} + h1 in ONE wave (fat tiles -- optimum per R12/R15)
        combo_k<<<128, NTHR, SMEM_BIG>>>(b_hh, b_h1);

        // [mean|raw] partials = h @ Wou (split-K=8, 256 CTAs)
        out_k<<<dim3(NO / 64, B / 64, SK), NTHR, SMEM_SML>>>();

        // reduce + bias, softplus, reparam sample
        epi_k<<<(B * S / 4 + 255) / 256, 256>>>(noise, b_out, out, t);
    }
}

// round 17
// speedup vs baseline: 1.2376x; 1.0266x over previous
#include <cuda_runtime.h>
#include <cuda_bf16.h>
#include <math.h>
#include <stdint.h>

// ---------------- problem constants ----------------
constexpr int B = 512, T = 64, S = 128, A = 32, H = 1024, R = 1024;
constexpr int KP = S + A;     // 160
constexpr int N3 = 3 * R;     // 3072
constexpr int NO = 2 * S;     // 256
constexpr int SK = 4;         // split-K for out GEMM (K-slice = 256)

constexpr int NTHR = 256;

constexpr size_t OFF_MEAN  = 0;
constexpr size_t OFF_STD   = OFF_MEAN  + (size_t)B * T * S;
constexpr size_t OFF_STATE = OFF_STD   + (size_t)B * T * S;
constexpr size_t OFF_BEL   = OFF_STATE + (size_t)B * T * S;
constexpr size_t OFF_PREV  = OFF_BEL   + (size_t)B * T * R;

// ---------------- device scratch ----------------
__device__ float g_gi[B * N3];
__device__ float g_gh[B * N3];
__device__ float g_belief[B * R];
__device__ float g_state [B * S];
__device__ float g_mo[SK * B * NO];

__device__ __nv_bfloat16 g_x_hi[B * H],   g_x_lo[B * H];
__device__ __nv_bfloat16 g_bel_hi[B * R], g_bel_lo[B * R];
__device__ __nv_bfloat16 g_h_hi[B * H],   g_h_lo[B * H];
__device__ __nv_bfloat16 g_Wpr_hi[H * KP], g_Wpr_lo[H * KP];
__device__ __nv_bfloat16 g_Wih_hi[N3 * H], g_Wih_lo[N3 * H];
__device__ __nv_bfloat16 g_Whh_hi[N3 * R], g_Whh_lo[N3 * R];
__device__ __nv_bfloat16 g_Wh1_hi[H * R],  g_Wh1_lo[H * R];
__device__ __nv_bfloat16 g_Wou_hi[NO * H], g_Wou_lo[NO * H];

// ---------------- PDL helper ----------------
__device__ __forceinline__ void pdl_wait() {
#if defined(__CUDA_ARCH__) && __CUDA_ARCH__ >= 900
    cudaGridDependencySynchronize();
#endif
}

// ---------------- portable PTX helpers (sm_80+) ----------------
__device__ __forceinline__ uint32_t smem_to_u32(const void* p) {
    uint32_t a;
    asm("{ .reg .u64 t; cvta.to.shared.u64 t, %1; cvt.u32.u64 %0, t; }" : "=r"(a) : "l"(p));
    return a;
}
__device__ __forceinline__ void cp16(uint32_t saddr, const void* gaddr) {
    asm volatile("cp.async.cg.shared.global [%0], [%1], 16;" :: "r"(saddr), "l"(gaddr) : "memory");
}
__device__ __forceinline__ void cp_commit() { asm volatile("cp.async.commit_group;" ::: "memory"); }
__device__ __forceinline__ void cp_wait1()  { asm volatile("cp.async.wait_group 1;" ::: "memory"); }

__device__ __forceinline__ void ldsm4(uint32_t a, uint32_t& r0, uint32_t& r1,
                                      uint32_t& r2, uint32_t& r3) {
    asm volatile("ldmatrix.sync.aligned.m8n8.x4.shared.b16 {%0,%1,%2,%3}, [%4];"
                 : "=r"(r0), "=r"(r1), "=r"(r2), "=r"(r3) : "r"(a));
}
__device__ __forceinline__ void mma_bf16(float* c, const uint32_t* a, const uint32_t* b) {
    asm volatile("mma.sync.aligned.m16n8k16.row.col.f32.bf16.bf16.f32 "
                 "{%0,%1,%2,%3},{%4,%5,%6,%7},{%8,%9},{%0,%1,%2,%3};"
                 : "+f"(c[0]), "+f"(c[1]), "+f"(c[2]), "+f"(c[3])
                 : "r"(a[0]), "r"(a[1]), "r"(a[2]), "r"(a[3]), "r"(b[0]), "r"(b[1]));
}
__device__ __forceinline__ float elu1(float v) { return (v > 0.f) ? v : expm1f(v); }

// ---------------- init ----------------
__global__ void init_k(const float* __restrict__ prior_state,
                       const float* __restrict__ belief0) {
    int idx = blockIdx.x * blockDim.x + threadIdx.x;
    if (idx < B * R) {
        float v = belief0[idx];
        g_belief[idx] = v;
        __nv_bfloat16 h = __float2bfloat16(v);
        g_bel_hi[idx] = h;
        g_bel_lo[idx] = __float2bfloat16(v - __bfloat162float(h));
    }
    if (idx < B * S) g_state[idx] = prior_state[idx];
}

// ---------------- weight prep: W[K][N] -> hi/lo[N][K] ----------------
__global__ void prep_w(const float* __restrict__ W, __nv_bfloat16* __restrict__ hi,
                       __nv_bfloat16* __restrict__ lo, int K, int N) {
    int idx = blockIdx.x * blockDim.x + threadIdx.x;
    if (idx >= N * K) return;
    int n = idx / K, k = idx % K;
    float v = W[(size_t)k * N + n];
    __nv_bfloat16 h = __float2bfloat16(v);
    hi[idx] = h;
    lo[idx] = __float2bfloat16(v - __bfloat162float(h));
}

// ---------------- bf16-split tensor-core GEMM tile, 3-stage pipeline ---------
template<int BM, int BN, int WRM, int WRN, int EPI, int PACKA>
__device__ __forceinline__ void gemm_tile(char* smem,
    const __nv_bfloat16* __restrict__ Ahi, const __nv_bfloat16* __restrict__ Alo,
    const __nv_bfloat16* __restrict__ Bhi, const __nv_bfloat16* __restrict__ Blo,
    const float* __restrict__ bias, float* __restrict__ Cf,
    __nv_bfloat16* __restrict__ Chi, __nv_bfloat16* __restrict__ Clo,
    const float* __restrict__ stateSrc, const float* __restrict__ actSrc, int tstep,
    int m0, int n0, int N, int K, int kz0, int KS)
{
    constexpr int THREADS = WRM * WRN * 32;
    constexpr int WTM = BM / WRM, WTN = BN / WRN;
    constexpr int MF = WTM / 16, NF = WTN / 8;
    constexpr int RS = 80;
    constexpr uint32_t OFS_AH = 0;
    constexpr uint32_t OFS_AL = (uint32_t)BM * RS;
    constexpr uint32_t OFS_BH = 2u * BM * RS;
    constexpr uint32_t OFS_BL = 2u * BM * RS + (uint32_t)BN * RS;
    constexpr uint32_t BUFSZ  = 2u * (BM + BN) * RS;

    const uint32_t sb = smem_to_u32(smem);
    const int tid = threadIdx.x;
    const int wid = tid >> 5, lane = tid & 31;
    const int wm = wid / WRN, wn = wid % WRN;

    const __nv_bfloat16* s0 = PACKA ? nullptr : Ahi + (size_t)m0 * K + kz0;
    const __nv_bfloat16* s1 = PACKA ? nullptr : Alo + (size_t)m0 * K + kz0;
    const __nv_bfloat16* s2 = Bhi + (size_t)n0 * K + kz0;
    const __nv_bfloat16* s3 = Blo + (size_t)n0 * K + kz0;

    const int NC = KS / 32;
    float acc[MF][NF][4];
    #pragma unroll
    for (int i = 0; i < MF; i++)
        #pragma unroll
        for (int j = 0; j < NF; j++)
            #pragma unroll
            for (int q = 0; q < 4; q++) acc[i][j][q] = 0.f;

    auto load_async = [&](int c, int buf) {
        uint32_t base = sb + (uint32_t)buf * BUFSZ;
        if constexpr (!PACKA) {
            constexpr int PPT = (BM + BN) * 8 / THREADS;
            #pragma unroll
            for (int i = 0; i < PPT; i++) {
                int p = tid + i * THREADS;
                const __nv_bfloat16* s;
                uint32_t ofs;
                int local;
                if (p < BM * 4)                   { s = s0; ofs = OFS_AH; local = p; }
                else if (p < 2 * BM * 4)          { s = s1; ofs = OFS_AL; local = p - BM * 4; }
                else if (p < 2 * BM * 4 + BN * 4) { s = s2; ofs = OFS_BH; local = p - 2 * BM * 4; }
                else                              { s = s3; ofs = OFS_BL; local = p - 2 * BM * 4 - BN * 4; }
                int row = local >> 2, k16 = local & 3;
                cp16(base + ofs + (uint32_t)row * RS + (uint32_t)k16 * 16,
                     s + (size_t)row * K + c * 32 + k16 * 8);
            }
        } else {
            constexpr int BPPT = BN * 8 / THREADS;
            #pragma unroll
            for (int i = 0; i < BPPT; i++) {
                int p = tid + i * THREADS;
                const __nv_bfloat16* s = (p < BN * 4) ? s2 : s3;
                uint32_t ofs = (p < BN * 4) ? OFS_BH : OFS_BL;
                int local = (p < BN * 4) ? p : p - BN * 4;
                int row = local >> 2, k16 = local & 3;
                cp16(base + ofs + (uint32_t)row * RS + (uint32_t)k16 * 16,
                     s + (size_t)row * K + c * 32 + k16 * 8);
            }
        }
    };

    auto load_A_pack = [&](int c, int buf) {
        if constexpr (PACKA) {
            char* bm = smem + (uint32_t)buf * BUFSZ;
            constexpr int APPT = BM * 4 / THREADS;
            #pragma unroll
            for (int i = 0; i < APPT; i++) {
                int slot = tid + i * THREADS;
                int row = slot >> 2, g8 = slot & 3;
                int kb = c * 32 + g8 * 8;
                __nv_bfloat16 hv[8], lv[8];
                #pragma unroll
                for (int j = 0; j < 8; j++) {
                    int col = kb + j;
                    float v = (col < S)
                        ? stateSrc[(size_t)(m0 + row) * S + col]
                        : actSrc[(size_t)(m0 + row) * T * A + (size_t)tstep * A + (col - S)];
                    __nv_bfloat16 h = __float2bfloat16(v);
                    hv[j] = h;
                    lv[j] = __float2bfloat16(v - __bfloat162float(h));
                }
                *(uint4*)(bm + OFS_AH + (uint32_t)row * RS + (uint32_t)g8 * 16) = *(uint4*)hv;
                *(uint4*)(bm + OFS_AL + (uint32_t)row * RS + (uint32_t)g8 * 16) = *(uint4*)lv;
            }
        }
    };

    auto mma_chunk = [&](int buf) {
        uint32_t base = sb + (uint32_t)buf * BUFSZ;
        const int grp = lane >> 3, l8 = lane & 7;
        #pragma unroll
        for (int ks = 0; ks < 2; ks++) {
            uint32_t ahi[MF][4], alo[MF][4], bhi[NF][2], blo[NF][2];
            uint32_t arow = (uint32_t)(wm * WTM + (grp & 1) * 8 + l8);
            uint32_t acol = (uint32_t)(ks * 32 + (grp >> 1) * 16);
            #pragma unroll
            for (int mt = 0; mt < MF; mt++) {
                uint32_t r = (arow + mt * 16) * RS + acol;
                ldsm4(base + OFS_AH + r, ahi[mt][0], ahi[mt][1], ahi[mt][2], ahi[mt][3]);
                ldsm4(base + OFS_AL + r, alo[mt][0], alo[mt][1], alo[mt][2], alo[mt][3]);
            }
            uint32_t brow = (uint32_t)(wn * WTN + (grp >> 1) * 8 + l8);
            uint32_t bcol = (uint32_t)(ks * 32 + (grp & 1) * 16);
            #pragma unroll
            for (int np = 0; np < NF / 2; np++) {
                uint32_t r = (brow + np * 16) * RS + bcol;
                ldsm4(base + OFS_BH + r, bhi[2 * np][0], bhi[2 * np][1],
                      bhi[2 * np + 1][0], bhi[2 * np + 1][1]);
                ldsm4(base + OFS_BL + r, blo[2 * np][0], blo[2 * np][1],
                      blo[2 * np + 1][0], blo[2 * np + 1][1]);
            }
            #pragma unroll
            for (int mt = 0; mt < MF; mt++)
                #pragma unroll
                for (int nt = 0; nt < NF; nt++) {
                    mma_bf16(acc[mt][nt], ahi[mt], bhi[nt]);
                    mma_bf16(acc[mt][nt], ahi[mt], blo[nt]);
                    mma_bf16(acc[mt][nt], alo[mt], bhi[nt]);
                }
        }
    };

    load_A_pack(0, 0);
    load_async(0, 0); cp_commit();
    if (NC > 1) { load_A_pack(1, 1); load_async(1, 1); }
    cp_commit();
    for (int c = 0; c < NC; c++) {
        cp_wait1();
        __syncthreads();
        mma_chunk(c % 3);
        if (c + 2 < NC) { load_A_pack(c + 2, (c + 2) % 3); load_async(c + 2, (c + 2) % 3); }
        cp_commit();
    }

    #pragma unroll
    for (int mt = 0; mt < MF; mt++)
        #pragma unroll
        for (int nt = 0; nt < NF; nt++) {
            int m = m0 + wm * WTM + mt * 16 + (lane >> 2);
            int n = n0 + wn * WTN + nt * 8 + (lane & 3) * 2;
            if constexpr (EPI == 3) {
                *(float2*)&Cf[(size_t)m * N + n] =
                    make_float2(acc[mt][nt][0], acc[mt][nt][1]);
                *(float2*)&Cf[(size_t)(m + 8) * N + n] =
                    make_float2(acc[mt][nt][2], acc[mt][nt][3]);
            } else if constexpr (EPI == 2) {
                float b0 = bias[n], b1 = bias[n + 1];
                float v00 = elu1(acc[mt][nt][0] + b0), v01 = elu1(acc[mt][nt][1] + b1);
                float v10 = elu1(acc[mt][nt][2] + b0), v11 = elu1(acc[mt][nt][3] + b1);
                __nv_bfloat16 h00 = __float2bfloat16(v00), h01 = __float2bfloat16(v01);
                __nv_bfloat16 h10 = __float2bfloat16(v10), h11 = __float2bfloat16(v11);
                __nv_bfloat162 hi0; hi0.x = h00; hi0.y = h01;
                __nv_bfloat162 hi1; hi1.x = h10; hi1.y = h11;
                __nv_bfloat162 lo0, lo1;
                lo0.x = __float2bfloat16(v00 - __bfloat162float(h00));
                lo0.y = __float2bfloat16(v01 - __bfloat162float(h01));
                lo1.x = __float2bfloat16(v10 - __bfloat162float(h10));
                lo1.y = __float2bfloat16(v11 - __bfloat162float(h11));
                *(__nv_bfloat162*)&Chi[(size_t)m * N + n] = hi0;
                *(__nv_bfloat162*)&Clo[(size_t)m * N + n] = lo0;
                *(__nv_bfloat162*)&Chi[(size_t)(m + 8) * N + n] = hi1;
                *(__nv_bfloat162*)&Clo[(size_t)(m + 8) * N + n] = lo1;
            } else {
                float b0 = bias[n], b1 = bias[n + 1];
                *(float2*)&Cf[(size_t)m * N + n] =
                    make_float2(acc[mt][nt][0] + b0, acc[mt][nt][1] + b1);
                *(float2*)&Cf[(size_t)(m + 8) * N + n] =
                    make_float2(acc[mt][nt][2] + b0, acc[mt][nt][3] + b1);
            }
        }
}

// ---------------- wrappers (each begins with a PDL dependency wait) ----------

// proj: x = elu([state|action_t] @ Wpr + b_proj) -> bf16 hi/lo. grid(16,8), 256 thr.
__global__ void __launch_bounds__(NTHR)
proj_k(const float* __restrict__ actions, const float* __restrict__ b_proj, int t) {
    extern __shared__ char smem[];
    pdl_wait();
    gemm_tile<64, 64, 2, 4, 2, 1>(smem, nullptr, nullptr, g_Wpr_hi, g_Wpr_lo,
        b_proj, nullptr, g_x_hi, g_x_lo, g_state, actions, t,
        blockIdx.y * 64, blockIdx.x * 64, H, KP, 0, KP);
}

// gi = x @ Wih + b_ih. 384 tiles of 64x64, 128 thr, 3 CTAs/SM -> all resident.
__global__ void __launch_bounds__(128, 3)
gi_k(const float* __restrict__ b_ih) {
    extern __shared__ char smem[];
    pdl_wait();
    gemm_tile<64, 64, 2, 2, 0, 0>(smem, g_x_hi, g_x_lo, g_Wih_hi, g_Wih_lo,
        b_ih, g_gi, nullptr, nullptr, nullptr, nullptr, 0,
        blockIdx.y * 64, blockIdx.x * 64, N3, H, 0, H);
}

// combo: gh_{t+1} (96 fat tiles 128x128) + h1 (32 fat tiles) = 128 CTAs, 1 wave.
__global__ void __launch_bounds__(NTHR)
combo_k(const float* __restrict__ b_hh, const float* __restrict__ b_h1) {
    extern __shared__ char smem[];
    pdl_wait();
    int tk = blockIdx.x;
    if (tk < 96) {
        int mi = tk / 24, ni = tk % 24;
        gemm_tile<128, 128, 2, 4, 0, 0>(smem, g_bel_hi, g_bel_lo, g_Whh_hi, g_Whh_lo,
            b_hh, g_gh, nullptr, nullptr, nullptr, nullptr, 0,
            mi * 128, ni * 128, N3, R, 0, R);
    } else {
        int u = tk - 96;
        int mi = u / 8, ni = u % 8;
        gemm_tile<128, 128, 2, 4, 2, 0>(smem, g_bel_hi, g_bel_lo, g_Wh1_hi, g_Wh1_lo,
            b_h1, nullptr, g_h_hi, g_h_lo, nullptr, nullptr, 0,
            mi * 128, ni * 128, H, R, 0, R);
    }
}

// gh only (prologue, t = 0)
__global__ void __launch_bounds__(NTHR)
gh0_k(const float* __restrict__ b_hh) {
    extern __shared__ char smem[];
    int tk = blockIdx.x;
    int mi = tk / 24, ni = tk % 24;
    gemm_tile<128, 128, 2, 4, 0, 0>(smem, g_bel_hi, g_bel_lo, g_Whh_hi, g_Whh_lo,
        b_hh, g_gh, nullptr, nullptr, nullptr, nullptr, 0,
        mi * 128, ni * 128, N3, R, 0, R);
}

// out: [mean|raw] partials = h @ Wou over K-slice of 256. grid(4,8,SK=4).
__global__ void __launch_bounds__(NTHR)
out_k() {
    extern __shared__ char smem[];
    pdl_wait();
    int z = blockIdx.z;
    gemm_tile<64, 64, 2, 4, 3, 0>(smem, g_h_hi, g_h_lo, g_Wou_hi, g_Wou_lo,
        nullptr, g_mo + (size_t)z * B * NO, nullptr, nullptr, nullptr, nullptr, 0,
        blockIdx.y * 64, blockIdx.x * 64, NO, H, z * (H / SK), H / SK);
}

// ---------------- GRU gate + belief update (float4 vectorized) ----------------
__global__ void gate_k(float* __restrict__ out, int t) {
    pdl_wait();
    int idx4 = blockIdx.x * blockDim.x + threadIdx.x;
    if (idx4 >= B * R / 4) return;
    int b = idx4 / (R / 4);
    int r = (idx4 % (R / 4)) * 4;
    size_t base = (size_t)b * N3;
    float4 ir = *(const float4*)&g_gi[base + r];
    float4 iz = *(const float4*)&g_gi[base + R + r];
    float4 in_ = *(const float4*)&g_gi[base + 2 * R + r];
    float4 hr = *(const float4*)&g_gh[base + r];
    float4 hz = *(const float4*)&g_gh[base + R + r];
    float4 hn = *(const float4*)&g_gh[base + 2 * R + r];
    float4 old = *(const float4*)&g_belief[b * R + r];

    float nb[4], ov[4] = {old.x, old.y, old.z, old.w};
    float irv[4] = {ir.x, ir.y, ir.z, ir.w}, izv[4] = {iz.x, iz.y, iz.z, iz.w};
    float inv[4] = {in_.x, in_.y, in_.z, in_.w};
    float hrv[4] = {hr.x, hr.y, hr.z, hr.w}, hzv[4] = {hz.x, hz.y, hz.z, hz.w};
    float hnv[4] = {hn.x, hn.y, hn.z, hn.w};
    #pragma unroll
    for (int j = 0; j < 4; j++) {
        float rg = 1.f / (1.f + expf(-(irv[j] + hrv[j])));
        float zg = 1.f / (1.f + expf(-(izv[j] + hzv[j])));
        float ng = tanhf(inv[j] + rg * hnv[j]);
        nb[j] = (1.f - zg) * ng + zg * ov[j];
    }
    *(float4*)&g_belief[b * R + r] = make_float4(nb[0], nb[1], nb[2], nb[3]);

    __nv_bfloat162 h01, h23, l01, l23;
    h01.x = __float2bfloat16(nb[0]); h01.y = __float2bfloat16(nb[1]);
    h23.x = __float2bfloat16(nb[2]); h23.y = __float2bfloat16(nb[3]);
    l01.x = __float2bfloat16(nb[0] - __bfloat162float(h01.x));
    l01.y = __float2bfloat16(nb[1] - __bfloat162float(h01.y));
    l23.x = __float2bfloat16(nb[2] - __bfloat162float(h23.x));
    l23.y = __float2bfloat16(nb[3] - __bfloat162float(h23.y));
    *(__nv_bfloat162*)&g_bel_hi[b * R + r]     = h01;
    *(__nv_bfloat162*)&g_bel_hi[b * R + r + 2] = h23;
    *(__nv_bfloat162*)&g_bel_lo[b * R + r]     = l01;
    *(__nv_bfloat162*)&g_bel_lo[b * R + r + 2] = l23;

    size_t o = (size_t)b * T * R + (size_t)t * R + r;
    *(float4*)&out[OFF_BEL + o]  = make_float4(nb[0], nb[1], nb[2], nb[3]);
    *(float4*)&out[OFF_PREV + o] = old;
}

// ---------------- epilogue: reduce split-K, softplus, sample (float4) --------
__global__ void epi_k(const float* __restrict__ noise,
                      const float* __restrict__ b_out,
                      float* __restrict__ out, int t) {
    pdl_wait();
    int idx4 = blockIdx.x * blockDim.x + threadIdx.x;
    if (idx4 >= B * S / 4) return;
    int b = idx4 / (S / 4);
    int s = (idx4 % (S / 4)) * 4;
    float4 mean = *(const float4*)&b_out[s];
    float4 raw  = *(const float4*)&b_out[S + s];
    float mv[4] = {mean.x, mean.y, mean.z, mean.w};
    float rv[4] = {raw.x, raw.y, raw.z, raw.w};
    #pragma unroll
    for (int z = 0; z < SK; z++) {
        const float* p = &g_mo[(size_t)z * B * NO + (size_t)b * NO];
        float4 pm = *(const float4*)&p[s];
        float4 pr = *(const float4*)&p[S + s];
        mv[0] += pm.x; mv[1] += pm.y; mv[2] += pm.z; mv[3] += pm.w;
        rv[0] += pr.x; rv[1] += pr.y; rv[2] += pr.z; rv[3] += pr.w;
    }
    float4 eps = *(const float4*)&noise[(size_t)b * T * S + (size_t)t * S + s];
    float ev[4] = {eps.x, eps.y, eps.z, eps.w};
    float sdv[4], stv[4];
    #pragma unroll
    for (int j = 0; j < 4; j++) {
        float sp = fmaxf(rv[j], 0.f) + log1pf(expf(-fabsf(rv[j])));
        sdv[j] = sp + 0.1f;
        stv[j] = fmaf(sdv[j], ev[j], mv[j]);
    }
    size_t o = (size_t)b * T * S + (size_t)t * S + s;
    *(float4*)&out[OFF_MEAN + o]  = make_float4(mv[0], mv[1], mv[2], mv[3]);
    *(float4*)&out[OFF_STD + o]   = make_float4(sdv[0], sdv[1], sdv[2], sdv[3]);
    *(float4*)&out[OFF_STATE + o] = make_float4(stv[0], stv[1], stv[2], stv[3]);
    *(float4*)&g_state[b * S + s] = make_float4(stv[0], stv[1], stv[2], stv[3]);
}

// ---------------- PDL launch helper ----------------
template <typename F, typename... Args>
static inline void launch_pdl(F kern, dim3 grid, dim3 block, uint32_t smem,
                              Args... args) {
    cudaLaunchAttribute attr[1];
    attr[0].id = cudaLaunchAttributeProgrammaticStreamSerialization;
    attr[0].val.programmaticStreamSerializationAllowed = 1;
    cudaLaunchConfig_t cfg = {};
    cfg.gridDim = grid;
    cfg.blockDim = block;
    cfg.dynamicSmemBytes = smem;
    cfg.stream = 0;
    cfg.attrs = attr;
    cfg.numAttrs = 1;
    cudaLaunchKernelEx(&cfg, kern, args...);
}

// ---------------- launch ----------------
extern "C" void kernel_launch(void* const* d_in, const int* in_sizes, int n_in,
                              void* d_out, int out_size) {
    const float* prior_state = (const float*)d_in[0];
    const float* belief0     = (const float*)d_in[1];
    const float* actions     = (const float*)d_in[2];
    const float* noise       = (const float*)d_in[3];
    const float* W_proj = (const float*)d_in[4];
    const float* b_proj = (const float*)d_in[5];
    const float* W_ih   = (const float*)d_in[6];
    const float* b_ih   = (const float*)d_in[7];
    const float* W_hh   = (const float*)d_in[8];
    const float* b_hh   = (const float*)d_in[9];
    const float* W_h1   = (const float*)d_in[10];
    const float* b_h1   = (const float*)d_in[11];
    const float* W_out  = (const float*)d_in[12];
    const float* b_out  = (const float*)d_in[13];
    float* out = (float*)d_out;

    __nv_bfloat16 *p_Wpr_h, *p_Wpr_l, *p_Wih_h, *p_Wih_l, *p_Whh_h, *p_Whh_l;
    __nv_bfloat16 *p_Wh1_h, *p_Wh1_l, *p_Wou_h, *p_Wou_l;
    cudaGetSymbolAddress((void**)&p_Wpr_h, g_Wpr_hi);
    cudaGetSymbolAddress((void**)&p_Wpr_l, g_Wpr_lo);
    cudaGetSymbolAddress((void**)&p_Wih_h, g_Wih_hi);
    cudaGetSymbolAddress((void**)&p_Wih_l, g_Wih_lo);
    cudaGetSymbolAddress((void**)&p_Whh_h, g_Whh_hi);
    cudaGetSymbolAddress((void**)&p_Whh_l, g_Whh_lo);
    cudaGetSymbolAddress((void**)&p_Wh1_h, g_Wh1_hi);
    cudaGetSymbolAddress((void**)&p_Wh1_l, g_Wh1_lo);
    cudaGetSymbolAddress((void**)&p_Wou_h, g_Wou_hi);
    cudaGetSymbolAddress((void**)&p_Wou_l, g_Wou_lo);

    constexpr uint32_t SMEM_BIG = 3u * 2u * (128 + 128) * 80;  // 122880
    constexpr uint32_t SMEM_SML = 3u * 2u * (64 + 64) * 80;    // 61440
    cudaFuncSetAttribute((const void*)proj_k,  cudaFuncAttributeMaxDynamicSharedMemorySize, SMEM_SML);
    cudaFuncSetAttribute((const void*)gi_k,    cudaFuncAttributeMaxDynamicSharedMemorySize, SMEM_SML);
    cudaFuncSetAttribute((const void*)combo_k, cudaFuncAttributeMaxDynamicSharedMemorySize, SMEM_BIG);
    cudaFuncSetAttribute((const void*)gh0_k,   cudaFuncAttributeMaxDynamicSharedMemorySize, SMEM_BIG);
    cudaFuncSetAttribute((const void*)out_k,   cudaFuncAttributeMaxDynamicSharedMemorySize, SMEM_SML);

    // one-time per replay: init recurrent state + weight split + gh_0
    init_k<<<(B * R + 255) / 256, 256>>>(prior_state, belief0);
    prep_w<<<(H * KP + 255) / 256, 256>>>(W_proj, p_Wpr_h, p_Wpr_l, KP, H);
    prep_w<<<(N3 * H + 255) / 256, 256>>>(W_ih, p_Wih_h, p_Wih_l, H, N3);
    prep_w<<<(N3 * R + 255) / 256, 256>>>(W_hh, p_Whh_h, p_Whh_l, R, N3);
    prep_w<<<(H * R + 255) / 256, 256>>>(W_h1, p_Wh1_h, p_Wh1_l, R, H);
    prep_w<<<(NO * H + 255) / 256, 256>>>(W_out, p_Wou_h, p_Wou_l, H, NO);
    gh0_k<<<96, NTHR, SMEM_BIG>>>(b_hh);

    for (int t = 0; t < T; t++) {
        // x = elu([state|action_t] @ Wpr + b_proj) (fused pack)
        launch_pdl(proj_k, dim3(H / 64, B / 64), dim3(NTHR), SMEM_SML,
                   actions, b_proj, t);

        // gi = x @ Wih + b_ih  -- 384 small tiles, all-SM balanced
        launch_pdl(gi_k, dim3(N3 / 64, B / 64), dim3(128), SMEM_SML, b_ih);

        // GRU gates -> new belief (+hi/lo), write beliefs + prev_beliefs
        launch_pdl(gate_k, dim3((B * R / 4 + 255) / 256), dim3(256), 0u, out, t);

        // gh_{t+1} + h1 in ONE wave (fat tiles)
        launch_pdl(combo_k, dim3(128), dim3(NTHR), SMEM_BIG, b_hh, b_h1);

        // [mean|raw] partials = h @ Wou (split-K=4)
        launch_pdl(out_k, dim3(NO / 64, B / 64, SK), dim3(NTHR), SMEM_SML);

        // reduce + bias, softplus, reparam sample
        launch_pdl(epi_k, dim3((B * S / 4 + 255) / 256), dim3(256), 0u,
                   noise, b_out, out, t);
    }
}